// round 1
// baseline (speedup 1.0000x reference)
#include <cuda_runtime.h>
#include <math.h>
#include <stdint.h>

// Problem shape (fixed by the reference)
#define BB 4
#define SS 2048
#define DD 1024
#define HH 16
#define HDIM 64
#define MROWS (BB * SS)          // 8192
#define QKV_LD (3 * DD)          // 3072

// Scratch: device globals (no cudaMalloc allowed)
__device__ float g_qkv[(size_t)MROWS * 3 * DD];   // [8192, 3072]
__device__ float g_y[(size_t)MROWS * DD];         // [8192, 1024]

// ---------------------------------------------------------------------------
// SGEMM: C[M,N] = A[M,K] @ B[K,N] + bias[N]
// 128x128 block tile, BK=16, 256 threads, 8x8 per-thread microtile.
// ---------------------------------------------------------------------------
__global__ __launch_bounds__(256) void sgemm_bias(
    const float* __restrict__ A, const float* __restrict__ B,
    const float* __restrict__ bias, float* __restrict__ C,
    int M, int N, int K)
{
    __shared__ float As[16][132];   // transposed A tile, padded vs bank conflicts
    __shared__ float Bs[16][128];

    const int tid = threadIdx.x;
    const int tx = tid & 15;        // column group (0..15)
    const int ty = tid >> 4;        // row group    (0..15)
    const int row0 = blockIdx.y * 128;
    const int col0 = blockIdx.x * 128;

    const float* Ap = A + (size_t)row0 * K;
    const float* Bp = B + col0;

    float acc[8][8];
#pragma unroll
    for (int i = 0; i < 8; i++)
#pragma unroll
        for (int j = 0; j < 8; j++) acc[i][j] = 0.0f;

    for (int k0 = 0; k0 < K; k0 += 16) {
        // Load A tile (128x16) and B tile (16x128), 2 float4 each per thread
#pragma unroll
        for (int t = 0; t < 2; t++) {
            int v = tid + t * 256;
            int ar = v >> 2;
            int ac = (v & 3) * 4;
            float4 a = *(const float4*)(Ap + (size_t)ar * K + k0 + ac);
            As[ac + 0][ar] = a.x;
            As[ac + 1][ar] = a.y;
            As[ac + 2][ar] = a.z;
            As[ac + 3][ar] = a.w;

            int br = v >> 5;
            int bc = (v & 31) * 4;
            *(float4*)&Bs[br][bc] = *(const float4*)(Bp + (size_t)(k0 + br) * N + bc);
        }
        __syncthreads();

#pragma unroll
        for (int k = 0; k < 16; k++) {
            float ra[8], rb[8];
            *(float4*)&ra[0] = *(const float4*)&As[k][ty * 8];
            *(float4*)&ra[4] = *(const float4*)&As[k][ty * 8 + 4];
            *(float4*)&rb[0] = *(const float4*)&Bs[k][tx * 8];
            *(float4*)&rb[4] = *(const float4*)&Bs[k][tx * 8 + 4];
#pragma unroll
            for (int i = 0; i < 8; i++)
#pragma unroll
                for (int j = 0; j < 8; j++)
                    acc[i][j] = fmaf(ra[i], rb[j], acc[i][j]);
        }
        __syncthreads();
    }

#pragma unroll
    for (int i = 0; i < 8; i++) {
        size_t r = (size_t)(row0 + ty * 8 + i);
#pragma unroll
        for (int j4 = 0; j4 < 2; j4++) {
            int c = col0 + tx * 8 + j4 * 4;
            float4 bv = *(const float4*)(bias + c);
            float4 w;
            w.x = acc[i][j4 * 4 + 0] + bv.x;
            w.y = acc[i][j4 * 4 + 1] + bv.y;
            w.z = acc[i][j4 * 4 + 2] + bv.z;
            w.w = acc[i][j4 * 4 + 3] + bv.w;
            *(float4*)(C + r * N + c) = w;
        }
    }
}

// ---------------------------------------------------------------------------
// Flash attention, fp32, causal. One block = one (b, h, 64-row q tile).
// 256 threads, 4x4 per-thread microtile of a 64x64 S / 64x64 O tile.
// qkv layout: [B*S, 3072] with q at col h*64, k at 1024+h*64, v at 2048+h*64.
// ---------------------------------------------------------------------------
#define FSM 68   // padded smem row stride (floats); 68*4B keeps float4 alignment

__global__ __launch_bounds__(256) void flash_attn(
    const float* __restrict__ qkv, float* __restrict__ y)
{
    extern __shared__ float sm[];
    float* Qs  = sm;                 // [64][FSM] row-major, pre-scaled by 1/8
    float* KPs = sm + 64 * FSM;      // first K^T: [d][j]; reused as P: [i][j]
    float* Vs  = sm + 2 * 64 * FSM;  // [j][c] row-major

    const int qt = blockIdx.x;       // q tile   (0..31)
    const int h  = blockIdx.y;       // head     (0..15)
    const int b  = blockIdx.z;       // batch    (0..3)
    const int tid = threadIdx.x;
    const int tx = tid & 15;
    const int ty = tid >> 4;

    const float* qbase = qkv + ((size_t)(b * SS) + qt * 64) * QKV_LD + h * HDIM;

    // Load Q tile (scaled by hd^-0.5 = 0.125)
    for (int v = tid; v < 64 * 16; v += 256) {
        int i  = v >> 4;
        int d4 = (v & 15) * 4;
        float4 q = *(const float4*)(qbase + (size_t)i * QKV_LD + d4);
        float* dst = Qs + i * FSM + d4;
        dst[0] = q.x * 0.125f;
        dst[1] = q.y * 0.125f;
        dst[2] = q.z * 0.125f;
        dst[3] = q.w * 0.125f;
    }

    float m_i[4], l_i[4], o[4][4];
#pragma unroll
    for (int m = 0; m < 4; m++) {
        m_i[m] = -1e30f;
        l_i[m] = 0.0f;
#pragma unroll
        for (int n = 0; n < 4; n++) o[m][n] = 0.0f;
    }

    for (int kt = 0; kt <= qt; kt++) {
        const float* kbase = qkv + ((size_t)(b * SS) + kt * 64) * QKV_LD + DD + h * HDIM;

        __syncthreads();   // previous iter's KPs(P)/Vs reads done (covers Qs on iter 0 via next sync)

        // Load K transposed + V row-major
        for (int v = tid; v < 64 * 16; v += 256) {
            int j  = v >> 4;
            int d4 = (v & 15) * 4;
            float4 kk = *(const float4*)(kbase + (size_t)j * QKV_LD + d4);
            KPs[(d4 + 0) * FSM + j] = kk.x;
            KPs[(d4 + 1) * FSM + j] = kk.y;
            KPs[(d4 + 2) * FSM + j] = kk.z;
            KPs[(d4 + 3) * FSM + j] = kk.w;
            float4 vv = *(const float4*)(kbase + DD + (size_t)j * QKV_LD + d4);
            *(float4*)(Vs + j * FSM + d4) = vv;
        }
        __syncthreads();

        // S = Q @ K^T (4x4 microtile per thread)
        float s[4][4];
#pragma unroll
        for (int m = 0; m < 4; m++)
#pragma unroll
            for (int n = 0; n < 4; n++) s[m][n] = 0.0f;

        for (int d = 0; d < 64; d++) {
            float4 rk = *(const float4*)(KPs + d * FSM + tx * 4);
            float rq0 = Qs[(ty * 4 + 0) * FSM + d];
            float rq1 = Qs[(ty * 4 + 1) * FSM + d];
            float rq2 = Qs[(ty * 4 + 2) * FSM + d];
            float rq3 = Qs[(ty * 4 + 3) * FSM + d];
            s[0][0] = fmaf(rq0, rk.x, s[0][0]); s[0][1] = fmaf(rq0, rk.y, s[0][1]);
            s[0][2] = fmaf(rq0, rk.z, s[0][2]); s[0][3] = fmaf(rq0, rk.w, s[0][3]);
            s[1][0] = fmaf(rq1, rk.x, s[1][0]); s[1][1] = fmaf(rq1, rk.y, s[1][1]);
            s[1][2] = fmaf(rq1, rk.z, s[1][2]); s[1][3] = fmaf(rq1, rk.w, s[1][3]);
            s[2][0] = fmaf(rq2, rk.x, s[2][0]); s[2][1] = fmaf(rq2, rk.y, s[2][1]);
            s[2][2] = fmaf(rq2, rk.z, s[2][2]); s[2][3] = fmaf(rq2, rk.w, s[2][3]);
            s[3][0] = fmaf(rq3, rk.x, s[3][0]); s[3][1] = fmaf(rq3, rk.y, s[3][1]);
            s[3][2] = fmaf(rq3, rk.z, s[3][2]); s[3][3] = fmaf(rq3, rk.w, s[3][3]);
        }

        // Causal mask on the diagonal tile
        if (kt == qt) {
#pragma unroll
            for (int m = 0; m < 4; m++)
#pragma unroll
                for (int n = 0; n < 4; n++)
                    if (tx * 4 + n > ty * 4 + m) s[m][n] = -1e30f;
        }

        // Online softmax update (row groups = 16 lanes sharing ty)
#pragma unroll
        for (int m = 0; m < 4; m++) {
            float mt = fmaxf(fmaxf(s[m][0], s[m][1]), fmaxf(s[m][2], s[m][3]));
#pragma unroll
            for (int off = 8; off > 0; off >>= 1)
                mt = fmaxf(mt, __shfl_xor_sync(0xffffffffu, mt, off));
            float mn = fmaxf(m_i[m], mt);
            float alpha = __expf(m_i[m] - mn);
            m_i[m] = mn;
            float rs = 0.0f;
#pragma unroll
            for (int n = 0; n < 4; n++) {
                s[m][n] = __expf(s[m][n] - mn);
                rs += s[m][n];
            }
#pragma unroll
            for (int off = 8; off > 0; off >>= 1)
                rs += __shfl_xor_sync(0xffffffffu, rs, off);
            l_i[m] = l_i[m] * alpha + rs;
#pragma unroll
            for (int n = 0; n < 4; n++) o[m][n] *= alpha;
        }

        __syncthreads();   // all threads done reading KPs as K^T

        // Store P into KPs (row-major [i][j])
#pragma unroll
        for (int m = 0; m < 4; m++)
            *(float4*)(KPs + (ty * 4 + m) * FSM + tx * 4) =
                make_float4(s[m][0], s[m][1], s[m][2], s[m][3]);
        __syncthreads();

        // O += P @ V
        for (int j = 0; j < 64; j++) {
            float4 v4 = *(const float4*)(Vs + j * FSM + tx * 4);
            float rp0 = KPs[(ty * 4 + 0) * FSM + j];
            float rp1 = KPs[(ty * 4 + 1) * FSM + j];
            float rp2 = KPs[(ty * 4 + 2) * FSM + j];
            float rp3 = KPs[(ty * 4 + 3) * FSM + j];
            o[0][0] = fmaf(rp0, v4.x, o[0][0]); o[0][1] = fmaf(rp0, v4.y, o[0][1]);
            o[0][2] = fmaf(rp0, v4.z, o[0][2]); o[0][3] = fmaf(rp0, v4.w, o[0][3]);
            o[1][0] = fmaf(rp1, v4.x, o[1][0]); o[1][1] = fmaf(rp1, v4.y, o[1][1]);
            o[1][2] = fmaf(rp1, v4.z, o[1][2]); o[1][3] = fmaf(rp1, v4.w, o[1][3]);
            o[2][0] = fmaf(rp2, v4.x, o[2][0]); o[2][1] = fmaf(rp2, v4.y, o[2][1]);
            o[2][2] = fmaf(rp2, v4.z, o[2][2]); o[2][3] = fmaf(rp2, v4.w, o[2][3]);
            o[3][0] = fmaf(rp3, v4.x, o[3][0]); o[3][1] = fmaf(rp3, v4.y, o[3][1]);
            o[3][2] = fmaf(rp3, v4.z, o[3][2]); o[3][3] = fmaf(rp3, v4.w, o[3][3]);
        }
    }

    // Write y[b, qt*64 + i, h*64 + c]  (head-concat layout)
    float* ybase = y + ((size_t)(b * SS) + qt * 64) * DD + h * HDIM;
#pragma unroll
    for (int m = 0; m < 4; m++) {
        float inv = 1.0f / l_i[m];
        *(float4*)(ybase + (size_t)(ty * 4 + m) * DD + tx * 4) =
            make_float4(o[m][0] * inv, o[m][1] * inv, o[m][2] * inv, o[m][3] * inv);
    }
}

#define FLASH_SMEM_BYTES (3 * 64 * FSM * sizeof(float))   // 52224

// ---------------------------------------------------------------------------
extern "C" void kernel_launch(void* const* d_in, const int* in_sizes, int n_in,
                              void* d_out, int out_size)
{
    const float* x      = (const float*)d_in[0];
    const float* W_attn = (const float*)d_in[1];
    const float* b_attn = (const float*)d_in[2];
    const float* W_proj = (const float*)d_in[3];
    const float* b_proj = (const float*)d_in[4];
    float* out = (float*)d_out;

    float *qkv, *y;
    cudaGetSymbolAddress((void**)&qkv, g_qkv);
    cudaGetSymbolAddress((void**)&y, g_y);

    cudaFuncSetAttribute(flash_attn, cudaFuncAttributeMaxDynamicSharedMemorySize,
                         (int)FLASH_SMEM_BYTES);

    // 1) qkv = x @ W_attn + b_attn         [8192,1024]x[1024,3072]
    sgemm_bias<<<dim3(3 * DD / 128, MROWS / 128), 256>>>(
        x, W_attn, b_attn, qkv, MROWS, 3 * DD, DD);

    // 2) y = causal_softmax(q k^T / 8) v   (per b, h)
    flash_attn<<<dim3(SS / 64, HH, BB), 256, FLASH_SMEM_BYTES>>>(qkv, y);

    // 3) out = y @ W_proj + b_proj         [8192,1024]x[1024,1024]
    sgemm_bias<<<dim3(DD / 128, MROWS / 128), 256>>>(
        y, W_proj, b_proj, out, MROWS, DD, DD);
}

// round 3
// speedup vs baseline: 1.4907x; 1.4907x over previous
#include <cuda_runtime.h>
#include <cuda_bf16.h>
#include <math.h>
#include <stdint.h>

// Problem shape (fixed by the reference)
#define BB 4
#define SS 2048
#define DD 1024
#define HH 16
#define HDIM 64
#define MROWS (BB * SS)          // 8192
#define QKV_LD (3 * DD)          // 3072
#define KDIM 1024

// ---------------------------------------------------------------------------
// Scratch: device globals (no cudaMalloc allowed)
// ---------------------------------------------------------------------------
__device__ float g_qkv[(size_t)MROWS * 3 * DD];            // [8192, 3072]
__device__ float g_y[(size_t)MROWS * DD];                  // [8192, 1024]
__device__ __nv_bfloat16 g_xh[(size_t)MROWS * KDIM];       // x hi/lo
__device__ __nv_bfloat16 g_xl[(size_t)MROWS * KDIM];
__device__ __nv_bfloat16 g_yh[(size_t)MROWS * KDIM];       // y hi/lo
__device__ __nv_bfloat16 g_yl[(size_t)MROWS * KDIM];
__device__ __nv_bfloat16 g_wah[(size_t)3 * DD * KDIM];     // W_attn^T hi/lo [N,K]
__device__ __nv_bfloat16 g_wal[(size_t)3 * DD * KDIM];
__device__ __nv_bfloat16 g_wph[(size_t)DD * KDIM];         // W_proj^T hi/lo [N,K]
__device__ __nv_bfloat16 g_wpl[(size_t)DD * KDIM];

// ---------------------------------------------------------------------------
// PTX helpers (base ISA only: cp.async / ldmatrix / mma.sync)
// ---------------------------------------------------------------------------
__device__ __forceinline__ uint32_t smem_u32(const void* p) {
    uint32_t a;
    asm("{ .reg .u64 t; cvta.to.shared.u64 t, %1; cvt.u32.u64 %0, t; }"
        : "=r"(a) : "l"(p));
    return a;
}

#define CP16(smem, gptr) \
    asm volatile("cp.async.cg.shared.global [%0], [%1], 16;" :: "r"(smem), "l"(gptr))
#define CP_COMMIT() asm volatile("cp.async.commit_group;" ::: "memory")
#define CP_WAIT(n)  asm volatile("cp.async.wait_group %0;" :: "n"(n) : "memory")

__device__ __forceinline__ void ldsm4(uint32_t* r, uint32_t addr) {
    asm volatile("ldmatrix.sync.aligned.m8n8.x4.shared.b16 {%0,%1,%2,%3}, [%4];"
                 : "=r"(r[0]), "=r"(r[1]), "=r"(r[2]), "=r"(r[3]) : "r"(addr));
}

__device__ __forceinline__ void mma16816(float* c, const uint32_t* a, const uint32_t* b) {
    asm volatile(
        "mma.sync.aligned.m16n8k16.row.col.f32.bf16.bf16.f32 "
        "{%0,%1,%2,%3}, {%4,%5,%6,%7}, {%8,%9}, {%0,%1,%2,%3};"
        : "+f"(c[0]), "+f"(c[1]), "+f"(c[2]), "+f"(c[3])
        : "r"(a[0]), "r"(a[1]), "r"(a[2]), "r"(a[3]), "r"(b[0]), "r"(b[1]));
}

// ---------------------------------------------------------------------------
// Split fp32 -> bf16 hi + bf16 lo (x = hi + lo, |err| ~ 2^-17 |x|)
// ---------------------------------------------------------------------------
__global__ __launch_bounds__(256) void split_kernel(
    const float* __restrict__ in, __nv_bfloat16* __restrict__ hi,
    __nv_bfloat16* __restrict__ lo, int n4)
{
    int i = blockIdx.x * 256 + threadIdx.x;
    if (i >= n4) return;
    float4 v = ((const float4*)in)[i];
    __nv_bfloat16 h0 = __float2bfloat16(v.x), h1 = __float2bfloat16(v.y);
    __nv_bfloat16 h2 = __float2bfloat16(v.z), h3 = __float2bfloat16(v.w);
    __nv_bfloat16 l0 = __float2bfloat16(v.x - __bfloat162float(h0));
    __nv_bfloat16 l1 = __float2bfloat16(v.y - __bfloat162float(h1));
    __nv_bfloat16 l2 = __float2bfloat16(v.z - __bfloat162float(h2));
    __nv_bfloat16 l3 = __float2bfloat16(v.w - __bfloat162float(h3));
    __nv_bfloat162* hp = (__nv_bfloat162*)hi;
    __nv_bfloat162* lp = (__nv_bfloat162*)lo;
    hp[2 * i + 0] = __halves2bfloat162(h0, h1);
    hp[2 * i + 1] = __halves2bfloat162(h2, h3);
    lp[2 * i + 0] = __halves2bfloat162(l0, l1);
    lp[2 * i + 1] = __halves2bfloat162(l2, l3);
}

// ---------------------------------------------------------------------------
// Transpose + split: W[K,N] fp32 -> Bt_hi/Bt_lo [N,K] bf16
// ---------------------------------------------------------------------------
__global__ void wsplit_t(const float* __restrict__ W, __nv_bfloat16* __restrict__ bh,
                         __nv_bfloat16* __restrict__ bl, int Kd, int Nd)
{
    __shared__ float t[32][33];
    int k0 = blockIdx.y * 32, n0 = blockIdx.x * 32;
    int tx = threadIdx.x, ty = threadIdx.y;   // block (32, 8)
    for (int r = ty; r < 32; r += 8)
        t[r][tx] = W[(size_t)(k0 + r) * Nd + n0 + tx];
    __syncthreads();
    for (int r = ty; r < 32; r += 8) {
        float v = t[tx][r];                    // = W[k0+tx][n0+r]
        __nv_bfloat16 h = __float2bfloat16(v);
        bh[(size_t)(n0 + r) * Kd + k0 + tx] = h;
        bl[(size_t)(n0 + r) * Kd + k0 + tx] = __float2bfloat16(v - __bfloat162float(h));
    }
}

// ---------------------------------------------------------------------------
// mma.sync bf16x3 GEMM: C[M,N] = (Ah+Al)[M,K] @ (Bh+Bl)[N,K]^T + bias
//
// CTA tile 128x128, BK=32, 256 threads = 8 warps (2M x 4N), warp tile 64x32.
// SMEM tiles stored as 64 physical rows x 128B with chunk^=(prow&7) swizzle:
//   logical (r, k) -> p = r>>1, chunk_log = (r&1)*4 + k/8,
//   byte = p*128 + (chunk_log ^ (p&7))*16 + (k%8)*2
// -> conflict-free cp.async stores AND conflict-free ldmatrix reads.
// ---------------------------------------------------------------------------
#define GBM 128
#define GBN 128
#define GBK 32
#define TILE_BYTES (64 * 128)                 // 8192 (128 rows x 32 bf16)
#define STAGE_BYTES (4 * TILE_BYTES)          // Ah, Al, Bh, Bl
#define NSTAGE 3
#define GEMM_SMEM (NSTAGE * STAGE_BYTES)      // 98304

// ldmatrix address for A-layout tile (rows = M), m16k16 fragment at (m0, ks)
__device__ __forceinline__ uint32_t a_addr(uint32_t tb, int m0, int ks, int lane) {
    int row = m0 + (lane & 15);
    int p = row >> 1;
    int chl = ((row & 1) << 2) | (ks << 1) | (lane >> 4);
    return tb + p * 128 + ((chl ^ (p & 7)) << 4);
}
// ldmatrix address for B-layout tile (rows = N), n16k16 fragment at (n0, ks)
__device__ __forceinline__ uint32_t b_addr(uint32_t tb, int n0, int ks, int lane) {
    int row = n0 + (lane & 7) + ((lane >> 4) << 3);
    int p = row >> 1;
    int chl = ((row & 1) << 2) | (ks << 1) | ((lane >> 3) & 1);
    return tb + p * 128 + ((chl ^ (p & 7)) << 4);
}

__global__ __launch_bounds__(256, 1) void gemm_mma_bf16x3(
    const __nv_bfloat16* __restrict__ Ah, const __nv_bfloat16* __restrict__ Al,
    const __nv_bfloat16* __restrict__ Bh, const __nv_bfloat16* __restrict__ Bl,
    const float* __restrict__ bias, float* __restrict__ C, int Nld)
{
    extern __shared__ __align__(1024) char smraw[];
    const uint32_t sbase = smem_u32(smraw);
    const int tid = threadIdx.x;
    const int lane = tid & 31;
    const int wid = tid >> 5;
    const int wm = wid & 1;      // 2 warp-rows of 64
    const int wn = wid >> 1;     // 4 warp-cols of 32
    const int row0 = blockIdx.y * GBM;
    const int col0 = blockIdx.x * GBN;

    const __nv_bfloat16* srcs[4];
    srcs[0] = Ah + (size_t)row0 * KDIM;
    srcs[1] = Al + (size_t)row0 * KDIM;
    srcs[2] = Bh + (size_t)col0 * KDIM;
    srcs[3] = Bl + (size_t)col0 * KDIM;

    float acc[4][4][4];
#pragma unroll
    for (int mi = 0; mi < 4; mi++)
#pragma unroll
        for (int ni = 0; ni < 4; ni++)
#pragma unroll
            for (int q = 0; q < 4; q++) acc[mi][ni][q] = 0.0f;

    // fill stage s with K-chunk c: 4 tiles x 512 chunks, 8 cp.async/thread
    auto fill = [&](int c, int s) {
        uint32_t stg = sbase + s * STAGE_BYTES;
#pragma unroll
        for (int t = 0; t < 4; t++) {
            uint32_t tb = stg + t * TILE_BYTES;
            const __nv_bfloat16* src = srcs[t] + c * GBK;
#pragma unroll
            for (int ii = 0; ii < 2; ii++) {
                int i = tid + ii * 256;
                int row = i >> 2, kc = i & 3;
                int p = row >> 1;
                int ch = (((row & 1) << 2) | kc) ^ (p & 7);
                CP16(tb + p * 128 + ch * 16, src + (size_t)row * KDIM + kc * 8);
            }
        }
        CP_COMMIT();
    };

    fill(0, 0);
    fill(1, 1);

    const int NCH = KDIM / GBK;   // 32
    for (int c = 0; c < NCH; c++) {
        int s = c % 3;
        if (c + 2 < NCH) { CP_WAIT(1); } else { CP_WAIT(0); }
        __syncthreads();
        if (c + 2 < NCH) fill(c + 2, (c + 2) % 3);

        uint32_t st = sbase + s * STAGE_BYTES;
#pragma unroll
        for (int ks = 0; ks < 2; ks++) {
            uint32_t aHf[4][4], aLf[4][4], bHf[2][4], bLf[2][4];
#pragma unroll
            for (int mi = 0; mi < 4; mi++) {
                ldsm4(aHf[mi], a_addr(st,              wm * 64 + mi * 16, ks, lane));
                ldsm4(aLf[mi], a_addr(st + TILE_BYTES, wm * 64 + mi * 16, ks, lane));
            }
#pragma unroll
            for (int g = 0; g < 2; g++) {
                ldsm4(bHf[g], b_addr(st + 2 * TILE_BYTES, wn * 32 + g * 16, ks, lane));
                ldsm4(bLf[g], b_addr(st + 3 * TILE_BYTES, wn * 32 + g * 16, ks, lane));
            }
#pragma unroll
            for (int mi = 0; mi < 4; mi++)
#pragma unroll
                for (int ni = 0; ni < 4; ni++) {
                    const uint32_t* bh = &bHf[ni >> 1][(ni & 1) * 2];
                    const uint32_t* bl = &bLf[ni >> 1][(ni & 1) * 2];
                    mma16816(acc[mi][ni], aHf[mi], bh);   // Ah*Bh
                    mma16816(acc[mi][ni], aHf[mi], bl);   // Ah*Bl
                    mma16816(acc[mi][ni], aLf[mi], bh);   // Al*Bh
                }
        }
    }

    // epilogue: fragment -> global, + bias
    const int qr = lane >> 2, qc = lane & 3;
#pragma unroll
    for (int mi = 0; mi < 4; mi++)
#pragma unroll
        for (int ni = 0; ni < 4; ni++) {
            int row = row0 + wm * 64 + mi * 16 + qr;
            int col = col0 + wn * 32 + ni * 8 + qc * 2;
            float2 bv = *(const float2*)(bias + col);
            float2 v0, v1;
            v0.x = acc[mi][ni][0] + bv.x;  v0.y = acc[mi][ni][1] + bv.y;
            v1.x = acc[mi][ni][2] + bv.x;  v1.y = acc[mi][ni][3] + bv.y;
            *(float2*)(C + (size_t)row * Nld + col) = v0;
            *(float2*)(C + (size_t)(row + 8) * Nld + col) = v1;
        }
}

// ---------------------------------------------------------------------------
// Flash attention, fp32, causal (unchanged from round 1 — known correct)
// ---------------------------------------------------------------------------
#define FSM 68

__global__ __launch_bounds__(256) void flash_attn(
    const float* __restrict__ qkv, float* __restrict__ y)
{
    extern __shared__ float smf[];
    float* Qs  = smf;
    float* KPs = smf + 64 * FSM;
    float* Vs  = smf + 2 * 64 * FSM;

    const int qt = blockIdx.x;
    const int h  = blockIdx.y;
    const int b  = blockIdx.z;
    const int tid = threadIdx.x;
    const int tx = tid & 15;
    const int ty = tid >> 4;

    const float* qbase = qkv + ((size_t)(b * SS) + qt * 64) * QKV_LD + h * HDIM;

    for (int v = tid; v < 64 * 16; v += 256) {
        int i  = v >> 4;
        int d4 = (v & 15) * 4;
        float4 q = *(const float4*)(qbase + (size_t)i * QKV_LD + d4);
        float* dst = Qs + i * FSM + d4;
        dst[0] = q.x * 0.125f;
        dst[1] = q.y * 0.125f;
        dst[2] = q.z * 0.125f;
        dst[3] = q.w * 0.125f;
    }

    float m_i[4], l_i[4], o[4][4];
#pragma unroll
    for (int m = 0; m < 4; m++) {
        m_i[m] = -1e30f;
        l_i[m] = 0.0f;
#pragma unroll
        for (int n = 0; n < 4; n++) o[m][n] = 0.0f;
    }

    for (int kt = 0; kt <= qt; kt++) {
        const float* kbase = qkv + ((size_t)(b * SS) + kt * 64) * QKV_LD + DD + h * HDIM;

        __syncthreads();

        for (int v = tid; v < 64 * 16; v += 256) {
            int j  = v >> 4;
            int d4 = (v & 15) * 4;
            float4 kk = *(const float4*)(kbase + (size_t)j * QKV_LD + d4);
            KPs[(d4 + 0) * FSM + j] = kk.x;
            KPs[(d4 + 1) * FSM + j] = kk.y;
            KPs[(d4 + 2) * FSM + j] = kk.z;
            KPs[(d4 + 3) * FSM + j] = kk.w;
            float4 vv = *(const float4*)(kbase + DD + (size_t)j * QKV_LD + d4);
            *(float4*)(Vs + j * FSM + d4) = vv;
        }
        __syncthreads();

        float s[4][4];
#pragma unroll
        for (int m = 0; m < 4; m++)
#pragma unroll
            for (int n = 0; n < 4; n++) s[m][n] = 0.0f;

        for (int d = 0; d < 64; d++) {
            float4 rk = *(const float4*)(KPs + d * FSM + tx * 4);
            float rq0 = Qs[(ty * 4 + 0) * FSM + d];
            float rq1 = Qs[(ty * 4 + 1) * FSM + d];
            float rq2 = Qs[(ty * 4 + 2) * FSM + d];
            float rq3 = Qs[(ty * 4 + 3) * FSM + d];
            s[0][0] = fmaf(rq0, rk.x, s[0][0]); s[0][1] = fmaf(rq0, rk.y, s[0][1]);
            s[0][2] = fmaf(rq0, rk.z, s[0][2]); s[0][3] = fmaf(rq0, rk.w, s[0][3]);
            s[1][0] = fmaf(rq1, rk.x, s[1][0]); s[1][1] = fmaf(rq1, rk.y, s[1][1]);
            s[1][2] = fmaf(rq1, rk.z, s[1][2]); s[1][3] = fmaf(rq1, rk.w, s[1][3]);
            s[2][0] = fmaf(rq2, rk.x, s[2][0]); s[2][1] = fmaf(rq2, rk.y, s[2][1]);
            s[2][2] = fmaf(rq2, rk.z, s[2][2]); s[2][3] = fmaf(rq2, rk.w, s[2][3]);
            s[3][0] = fmaf(rq3, rk.x, s[3][0]); s[3][1] = fmaf(rq3, rk.y, s[3][1]);
            s[3][2] = fmaf(rq3, rk.z, s[3][2]); s[3][3] = fmaf(rq3, rk.w, s[3][3]);
        }

        if (kt == qt) {
#pragma unroll
            for (int m = 0; m < 4; m++)
#pragma unroll
                for (int n = 0; n < 4; n++)
                    if (tx * 4 + n > ty * 4 + m) s[m][n] = -1e30f;
        }

#pragma unroll
        for (int m = 0; m < 4; m++) {
            float mt = fmaxf(fmaxf(s[m][0], s[m][1]), fmaxf(s[m][2], s[m][3]));
#pragma unroll
            for (int off = 8; off > 0; off >>= 1)
                mt = fmaxf(mt, __shfl_xor_sync(0xffffffffu, mt, off));
            float mn = fmaxf(m_i[m], mt);
            float alpha = __expf(m_i[m] - mn);
            m_i[m] = mn;
            float rs = 0.0f;
#pragma unroll
            for (int n = 0; n < 4; n++) {
                s[m][n] = __expf(s[m][n] - mn);
                rs += s[m][n];
            }
#pragma unroll
            for (int off = 8; off > 0; off >>= 1)
                rs += __shfl_xor_sync(0xffffffffu, rs, off);
            l_i[m] = l_i[m] * alpha + rs;
#pragma unroll
            for (int n = 0; n < 4; n++) o[m][n] *= alpha;
        }

        __syncthreads();

#pragma unroll
        for (int m = 0; m < 4; m++)
            *(float4*)(KPs + (ty * 4 + m) * FSM + tx * 4) =
                make_float4(s[m][0], s[m][1], s[m][2], s[m][3]);
        __syncthreads();

        for (int j = 0; j < 64; j++) {
            float4 v4 = *(const float4*)(Vs + j * FSM + tx * 4);
            float rp0 = KPs[(ty * 4 + 0) * FSM + j];
            float rp1 = KPs[(ty * 4 + 1) * FSM + j];
            float rp2 = KPs[(ty * 4 + 2) * FSM + j];
            float rp3 = KPs[(ty * 4 + 3) * FSM + j];
            o[0][0] = fmaf(rp0, v4.x, o[0][0]); o[0][1] = fmaf(rp0, v4.y, o[0][1]);
            o[0][2] = fmaf(rp0, v4.z, o[0][2]); o[0][3] = fmaf(rp0, v4.w, o[0][3]);
            o[1][0] = fmaf(rp1, v4.x, o[1][0]); o[1][1] = fmaf(rp1, v4.y, o[1][1]);
            o[1][2] = fmaf(rp1, v4.z, o[1][2]); o[1][3] = fmaf(rp1, v4.w, o[1][3]);
            o[2][0] = fmaf(rp2, v4.x, o[2][0]); o[2][1] = fmaf(rp2, v4.y, o[2][1]);
            o[2][2] = fmaf(rp2, v4.z, o[2][2]); o[2][3] = fmaf(rp2, v4.w, o[2][3]);
            o[3][0] = fmaf(rp3, v4.x, o[3][0]); o[3][1] = fmaf(rp3, v4.y, o[3][1]);
            o[3][2] = fmaf(rp3, v4.z, o[3][2]); o[3][3] = fmaf(rp3, v4.w, o[3][3]);
        }
    }

    float* ybase = y + ((size_t)(b * SS) + qt * 64) * DD + h * HDIM;
#pragma unroll
    for (int m = 0; m < 4; m++) {
        float inv = 1.0f / l_i[m];
        *(float4*)(ybase + (size_t)(ty * 4 + m) * DD + tx * 4) =
            make_float4(o[m][0] * inv, o[m][1] * inv, o[m][2] * inv, o[m][3] * inv);
    }
}

#define FLASH_SMEM_BYTES (3 * 64 * FSM * sizeof(float))

// ---------------------------------------------------------------------------
extern "C" void kernel_launch(void* const* d_in, const int* in_sizes, int n_in,
                              void* d_out, int out_size)
{
    const float* x      = (const float*)d_in[0];
    const float* W_attn = (const float*)d_in[1];
    const float* b_attn = (const float*)d_in[2];
    const float* W_proj = (const float*)d_in[3];
    const float* b_proj = (const float*)d_in[4];
    float* out = (float*)d_out;

    float *qkv, *y;
    __nv_bfloat16 *xh, *xl, *yh, *yl, *wah, *wal, *wph, *wpl;
    cudaGetSymbolAddress((void**)&qkv, g_qkv);
    cudaGetSymbolAddress((void**)&y,   g_y);
    cudaGetSymbolAddress((void**)&xh,  g_xh);
    cudaGetSymbolAddress((void**)&xl,  g_xl);
    cudaGetSymbolAddress((void**)&yh,  g_yh);
    cudaGetSymbolAddress((void**)&yl,  g_yl);
    cudaGetSymbolAddress((void**)&wah, g_wah);
    cudaGetSymbolAddress((void**)&wal, g_wal);
    cudaGetSymbolAddress((void**)&wph, g_wph);
    cudaGetSymbolAddress((void**)&wpl, g_wpl);

    cudaFuncSetAttribute(gemm_mma_bf16x3, cudaFuncAttributeMaxDynamicSharedMemorySize,
                         (int)GEMM_SMEM);
    cudaFuncSetAttribute(flash_attn, cudaFuncAttributeMaxDynamicSharedMemorySize,
                         (int)FLASH_SMEM_BYTES);

    // convert inputs
    split_kernel<<<(MROWS * KDIM / 4 + 255) / 256, 256>>>(x, xh, xl, MROWS * KDIM / 4);
    wsplit_t<<<dim3(3 * DD / 32, KDIM / 32), dim3(32, 8)>>>(W_attn, wah, wal, KDIM, 3 * DD);
    wsplit_t<<<dim3(DD / 32, KDIM / 32), dim3(32, 8)>>>(W_proj, wph, wpl, KDIM, DD);

    // 1) qkv = x @ W_attn + b_attn
    gemm_mma_bf16x3<<<dim3(3 * DD / GBN, MROWS / GBM), 256, GEMM_SMEM>>>(
        xh, xl, wah, wal, b_attn, qkv, 3 * DD);

    // 2) attention
    flash_attn<<<dim3(SS / 64, HH, BB), 256, FLASH_SMEM_BYTES>>>(qkv, y);

    // 3) out = y @ W_proj + b_proj
    split_kernel<<<(MROWS * KDIM / 4 + 255) / 256, 256>>>(y, yh, yl, MROWS * KDIM / 4);
    gemm_mma_bf16x3<<<dim3(DD / GBN, MROWS / GBM), 256, GEMM_SMEM>>>(
        yh, yl, wph, wpl, b_proj, out, DD);
}

// round 4
// speedup vs baseline: 2.8157x; 1.8889x over previous
#include <cuda_runtime.h>
#include <cuda_bf16.h>
#include <math.h>
#include <stdint.h>

// Problem shape (fixed by the reference)
#define BB 4
#define SS 2048
#define DD 1024
#define HH 16
#define HDIM 64
#define MROWS (BB * SS)          // 8192
#define KDIM 1024

// ---------------------------------------------------------------------------
// Scratch: device globals (no cudaMalloc allowed)
// ---------------------------------------------------------------------------
__device__ __nv_bfloat16 g_xh[(size_t)MROWS * KDIM];
__device__ __nv_bfloat16 g_xl[(size_t)MROWS * KDIM];
__device__ __nv_bfloat16 g_qh[(size_t)MROWS * DD];
__device__ __nv_bfloat16 g_ql[(size_t)MROWS * DD];
__device__ __nv_bfloat16 g_kh[(size_t)MROWS * DD];
__device__ __nv_bfloat16 g_kl[(size_t)MROWS * DD];
__device__ __nv_bfloat16 g_vh[(size_t)MROWS * DD];
__device__ __nv_bfloat16 g_vl[(size_t)MROWS * DD];
__device__ __nv_bfloat16 g_yh[(size_t)MROWS * KDIM];
__device__ __nv_bfloat16 g_yl[(size_t)MROWS * KDIM];
__device__ __nv_bfloat16 g_wah[(size_t)3 * DD * KDIM];   // W_attn^T hi/lo [N,K]
__device__ __nv_bfloat16 g_wal[(size_t)3 * DD * KDIM];
__device__ __nv_bfloat16 g_wph[(size_t)DD * KDIM];       // W_proj^T hi/lo [N,K]
__device__ __nv_bfloat16 g_wpl[(size_t)DD * KDIM];

// ---------------------------------------------------------------------------
// PTX helpers (base ISA only: cp.async / ldmatrix / mma.sync)
// ---------------------------------------------------------------------------
__device__ __forceinline__ uint32_t smem_u32(const void* p) {
    uint32_t a;
    asm("{ .reg .u64 t; cvta.to.shared.u64 t, %1; cvt.u32.u64 %0, t; }"
        : "=r"(a) : "l"(p));
    return a;
}

#define CP16(smem, gptr) \
    asm volatile("cp.async.cg.shared.global [%0], [%1], 16;" :: "r"(smem), "l"(gptr))
#define CP_COMMIT() asm volatile("cp.async.commit_group;" ::: "memory")
#define CP_WAIT(n)  asm volatile("cp.async.wait_group %0;" :: "n"(n) : "memory")

__device__ __forceinline__ void ldsm4(uint32_t* r, uint32_t addr) {
    asm volatile("ldmatrix.sync.aligned.m8n8.x4.shared.b16 {%0,%1,%2,%3}, [%4];"
                 : "=r"(r[0]), "=r"(r[1]), "=r"(r[2]), "=r"(r[3]) : "r"(addr));
}
__device__ __forceinline__ void ldsm4t(uint32_t* r, uint32_t addr) {
    asm volatile("ldmatrix.sync.aligned.m8n8.x4.trans.shared.b16 {%0,%1,%2,%3}, [%4];"
                 : "=r"(r[0]), "=r"(r[1]), "=r"(r[2]), "=r"(r[3]) : "r"(addr));
}

__device__ __forceinline__ void mma16816(float* c, const uint32_t* a, const uint32_t* b) {
    asm volatile(
        "mma.sync.aligned.m16n8k16.row.col.f32.bf16.bf16.f32 "
        "{%0,%1,%2,%3}, {%4,%5,%6,%7}, {%8,%9}, {%0,%1,%2,%3};"
        : "+f"(c[0]), "+f"(c[1]), "+f"(c[2]), "+f"(c[3])
        : "r"(a[0]), "r"(a[1]), "r"(a[2]), "r"(a[3]), "r"(b[0]), "r"(b[1]));
}

__device__ __forceinline__ uint32_t pack_bf2(float a, float b) {
    __nv_bfloat162 t = __floats2bfloat162_rn(a, b);
    return *(uint32_t*)&t;
}

// ---------------------------------------------------------------------------
// Split fp32 -> bf16 hi + bf16 lo
// ---------------------------------------------------------------------------
__global__ __launch_bounds__(256) void split_kernel(
    const float* __restrict__ in, __nv_bfloat16* __restrict__ hi,
    __nv_bfloat16* __restrict__ lo, int n4)
{
    int i = blockIdx.x * 256 + threadIdx.x;
    if (i >= n4) return;
    float4 v = ((const float4*)in)[i];
    __nv_bfloat16 h0 = __float2bfloat16(v.x), h1 = __float2bfloat16(v.y);
    __nv_bfloat16 h2 = __float2bfloat16(v.z), h3 = __float2bfloat16(v.w);
    __nv_bfloat162* hp = (__nv_bfloat162*)hi;
    __nv_bfloat162* lp = (__nv_bfloat162*)lo;
    hp[2 * i + 0] = __halves2bfloat162(h0, h1);
    hp[2 * i + 1] = __halves2bfloat162(h2, h3);
    lp[2 * i + 0] = __floats2bfloat162_rn(v.x - __bfloat162float(h0),
                                          v.y - __bfloat162float(h1));
    lp[2 * i + 1] = __floats2bfloat162_rn(v.z - __bfloat162float(h2),
                                          v.w - __bfloat162float(h3));
}

// ---------------------------------------------------------------------------
// Transpose + split: W[K,N] fp32 -> Bt_hi/Bt_lo [N,K] bf16
// ---------------------------------------------------------------------------
__global__ void wsplit_t(const float* __restrict__ W, __nv_bfloat16* __restrict__ bh,
                         __nv_bfloat16* __restrict__ bl, int Kd, int Nd)
{
    __shared__ float t[32][33];
    int k0 = blockIdx.y * 32, n0 = blockIdx.x * 32;
    int tx = threadIdx.x, ty = threadIdx.y;   // block (32, 8)
    for (int r = ty; r < 32; r += 8)
        t[r][tx] = W[(size_t)(k0 + r) * Nd + n0 + tx];
    __syncthreads();
    for (int r = ty; r < 32; r += 8) {
        float v = t[tx][r];
        __nv_bfloat16 h = __float2bfloat16(v);
        bh[(size_t)(n0 + r) * Kd + k0 + tx] = h;
        bl[(size_t)(n0 + r) * Kd + k0 + tx] = __float2bfloat16(v - __bfloat162float(h));
    }
}

// ---------------------------------------------------------------------------
// mma.sync bf16x3 GEMM (same mainloop as round 3, now with two epilogues):
//   mode 0: C = acc + bias (fp32)
//   mode 1: split-write into q/k/v hi+lo bf16 arrays (q scaled by 0.125)
// ---------------------------------------------------------------------------
#define GBM 128
#define GBN 128
#define GBK 32
#define TILE_BYTES (64 * 128)
#define STAGE_BYTES (4 * TILE_BYTES)
#define NSTAGE 3
#define GEMM_SMEM (NSTAGE * STAGE_BYTES)

__device__ __forceinline__ uint32_t a_addr(uint32_t tb, int m0, int ks, int lane) {
    int row = m0 + (lane & 15);
    int p = row >> 1;
    int chl = ((row & 1) << 2) | (ks << 1) | (lane >> 4);
    return tb + p * 128 + ((chl ^ (p & 7)) << 4);
}
__device__ __forceinline__ uint32_t b_addr(uint32_t tb, int n0, int ks, int lane) {
    int row = n0 + (lane & 7) + ((lane >> 4) << 3);
    int p = row >> 1;
    int chl = ((row & 1) << 2) | (ks << 1) | ((lane >> 3) & 1);
    return tb + p * 128 + ((chl ^ (p & 7)) << 4);
}

__global__ __launch_bounds__(256, 1) void gemm_mma_bf16x3(
    const __nv_bfloat16* __restrict__ Ah, const __nv_bfloat16* __restrict__ Al,
    const __nv_bfloat16* __restrict__ Bh, const __nv_bfloat16* __restrict__ Bl,
    const float* __restrict__ bias, float* __restrict__ C, int Nld, int mode,
    __nv_bfloat16* __restrict__ oqh, __nv_bfloat16* __restrict__ oql,
    __nv_bfloat16* __restrict__ okh, __nv_bfloat16* __restrict__ okl,
    __nv_bfloat16* __restrict__ ovh, __nv_bfloat16* __restrict__ ovl)
{
    extern __shared__ __align__(1024) char smraw[];
    const uint32_t sbase = smem_u32(smraw);
    const int tid = threadIdx.x;
    const int lane = tid & 31;
    const int wid = tid >> 5;
    const int wm = wid & 1;
    const int wn = wid >> 1;
    const int row0 = blockIdx.y * GBM;
    const int col0 = blockIdx.x * GBN;

    const __nv_bfloat16* srcs[4];
    srcs[0] = Ah + (size_t)row0 * KDIM;
    srcs[1] = Al + (size_t)row0 * KDIM;
    srcs[2] = Bh + (size_t)col0 * KDIM;
    srcs[3] = Bl + (size_t)col0 * KDIM;

    float acc[4][4][4];
#pragma unroll
    for (int mi = 0; mi < 4; mi++)
#pragma unroll
        for (int ni = 0; ni < 4; ni++)
#pragma unroll
            for (int q = 0; q < 4; q++) acc[mi][ni][q] = 0.0f;

    auto fill = [&](int c, int s) {
        uint32_t stg = sbase + s * STAGE_BYTES;
#pragma unroll
        for (int t = 0; t < 4; t++) {
            uint32_t tb = stg + t * TILE_BYTES;
            const __nv_bfloat16* src = srcs[t] + c * GBK;
#pragma unroll
            for (int ii = 0; ii < 2; ii++) {
                int i = tid + ii * 256;
                int row = i >> 2, kc = i & 3;
                int p = row >> 1;
                int ch = (((row & 1) << 2) | kc) ^ (p & 7);
                CP16(tb + p * 128 + ch * 16, src + (size_t)row * KDIM + kc * 8);
            }
        }
        CP_COMMIT();
    };

    fill(0, 0);
    fill(1, 1);

    const int NCH = KDIM / GBK;   // 32
    for (int c = 0; c < NCH; c++) {
        int s = c % 3;
        if (c + 2 < NCH) { CP_WAIT(1); } else { CP_WAIT(0); }
        __syncthreads();
        if (c + 2 < NCH) fill(c + 2, (c + 2) % 3);

        uint32_t st = sbase + s * STAGE_BYTES;
#pragma unroll
        for (int ks = 0; ks < 2; ks++) {
            uint32_t aHf[4][4], aLf[4][4], bHf[2][4], bLf[2][4];
#pragma unroll
            for (int mi = 0; mi < 4; mi++) {
                ldsm4(aHf[mi], a_addr(st,              wm * 64 + mi * 16, ks, lane));
                ldsm4(aLf[mi], a_addr(st + TILE_BYTES, wm * 64 + mi * 16, ks, lane));
            }
#pragma unroll
            for (int g = 0; g < 2; g++) {
                ldsm4(bHf[g], b_addr(st + 2 * TILE_BYTES, wn * 32 + g * 16, ks, lane));
                ldsm4(bLf[g], b_addr(st + 3 * TILE_BYTES, wn * 32 + g * 16, ks, lane));
            }
#pragma unroll
            for (int mi = 0; mi < 4; mi++)
#pragma unroll
                for (int ni = 0; ni < 4; ni++) {
                    const uint32_t* bh = &bHf[ni >> 1][(ni & 1) * 2];
                    const uint32_t* bl = &bLf[ni >> 1][(ni & 1) * 2];
                    mma16816(acc[mi][ni], aHf[mi], bh);
                    mma16816(acc[mi][ni], aHf[mi], bl);
                    mma16816(acc[mi][ni], aLf[mi], bh);
                }
        }
    }

    const int qr = lane >> 2, qc = lane & 3;
    if (mode == 0) {
#pragma unroll
        for (int mi = 0; mi < 4; mi++)
#pragma unroll
            for (int ni = 0; ni < 4; ni++) {
                int row = row0 + wm * 64 + mi * 16 + qr;
                int col = col0 + wn * 32 + ni * 8 + qc * 2;
                float2 bv = *(const float2*)(bias + col);
                float2 v0, v1;
                v0.x = acc[mi][ni][0] + bv.x;  v0.y = acc[mi][ni][1] + bv.y;
                v1.x = acc[mi][ni][2] + bv.x;  v1.y = acc[mi][ni][3] + bv.y;
                *(float2*)(C + (size_t)row * Nld + col) = v0;
                *(float2*)(C + (size_t)(row + 8) * Nld + col) = v1;
            }
    } else {
        // split-write epilogue: tensor id from column block (0=q, 1=k, 2=v)
        int t = col0 >> 10;
        __nv_bfloat16* oh = (t == 0) ? oqh : (t == 1) ? okh : ovh;
        __nv_bfloat16* ol = (t == 0) ? oql : (t == 1) ? okl : ovl;
        float sc = (t == 0) ? 0.125f : 1.0f;   // fold hd^-0.5 into q (exact pow2)
#pragma unroll
        for (int mi = 0; mi < 4; mi++)
#pragma unroll
            for (int ni = 0; ni < 4; ni++) {
                int row = row0 + wm * 64 + mi * 16 + qr;
                int gcol = col0 + wn * 32 + ni * 8 + qc * 2;
                int lcol = gcol & 1023;
                float2 bv = *(const float2*)(bias + gcol);
                float x0 = (acc[mi][ni][0] + bv.x) * sc;
                float x1 = (acc[mi][ni][1] + bv.y) * sc;
                float x2 = (acc[mi][ni][2] + bv.x) * sc;
                float x3 = (acc[mi][ni][3] + bv.y) * sc;
                __nv_bfloat16 h0 = __float2bfloat16(x0), h1 = __float2bfloat16(x1);
                __nv_bfloat16 h2 = __float2bfloat16(x2), h3 = __float2bfloat16(x3);
                size_t i0 = (size_t)row * DD + lcol;
                size_t i1 = (size_t)(row + 8) * DD + lcol;
                *(__nv_bfloat162*)(oh + i0) = __halves2bfloat162(h0, h1);
                *(__nv_bfloat162*)(oh + i1) = __halves2bfloat162(h2, h3);
                *(__nv_bfloat162*)(ol + i0) = __floats2bfloat162_rn(
                    x0 - __bfloat162float(h0), x1 - __bfloat162float(h1));
                *(__nv_bfloat162*)(ol + i1) = __floats2bfloat162_rn(
                    x2 - __bfloat162float(h2), x3 - __bfloat162float(h3));
            }
    }
}

// ---------------------------------------------------------------------------
// Flash attention with mma.sync, bf16x3, causal.
// CTA = (b, h, 128-row q tile), 256 threads = 8 warps, warp = 16 q rows.
// K/V tiles 128x64, double-buffered via cp.async.
// SMEM tiles: [rows][64 bf16 = 128B row], SW128 swizzle (chunk ^= row&7).
// ---------------------------------------------------------------------------
#define ATT_TILE_B 16384                       // 128 rows x 128 B
#define ATT_KV_STAGE (4 * ATT_TILE_B)          // Kh, Kl, Vh, Vl
#define ATT_SMEM (2 * ATT_TILE_B + 2 * ATT_KV_STAGE)   // 163840

__device__ __forceinline__ uint32_t sw128(uint32_t tb, int row, int chunk) {
    return tb + row * 128 + ((chunk ^ (row & 7)) << 4);
}
// A fragment (rows = m), 128B rows
__device__ __forceinline__ uint32_t fa_a(uint32_t tb, int m0, int ks, int lane) {
    int row = m0 + (lane & 15);
    return sw128(tb, row, ks * 2 + (lane >> 4));
}
// B fragment from K (rows = n), 128B rows
__device__ __forceinline__ uint32_t fa_b(uint32_t tb, int n0, int ks, int lane) {
    int row = n0 + (lane & 7) + ((lane >> 4) << 3);
    return sw128(tb, row, ks * 2 + ((lane >> 3) & 1));
}
// B fragment from V via ldmatrix.trans (rows = kv, cols = hd)
__device__ __forceinline__ uint32_t fa_v(uint32_t tb, int kv0, int hd0, int lane) {
    int row = kv0 + (((lane >> 3) & 1) << 3) + (lane & 7);
    return sw128(tb, row, (hd0 >> 3) + (lane >> 4));
}

__global__ __launch_bounds__(256, 1) void flash_attn_mma(
    const __nv_bfloat16* __restrict__ qh, const __nv_bfloat16* __restrict__ ql,
    const __nv_bfloat16* __restrict__ kh, const __nv_bfloat16* __restrict__ kl,
    const __nv_bfloat16* __restrict__ vh, const __nv_bfloat16* __restrict__ vl,
    __nv_bfloat16* __restrict__ yh, __nv_bfloat16* __restrict__ yl)
{
    extern __shared__ __align__(1024) char smraw[];
    const uint32_t sb = smem_u32(smraw);
    const int qt = blockIdx.x, h = blockIdx.y, b = blockIdx.z;
    const int tid = threadIdx.x, lane = tid & 31, w = tid >> 5;
    const size_t rowbase = (size_t)(b * SS) + qt * 128;
    const int hoff = h * HDIM;

    const uint32_t sQh = sb, sQl = sb + ATT_TILE_B;
    const uint32_t sKV = sb + 2 * ATT_TILE_B;

    // one-time Q load (group 1)
    {
        const __nv_bfloat16* qs[2] = {qh, ql};
        for (int i = tid; i < 2048; i += 256) {
            int t = i >> 10, idx = i & 1023, r = idx >> 3, ch = idx & 7;
            CP16(sw128(t ? sQl : sQh, r, ch),
                 qs[t] + (rowbase + r) * DD + hoff + ch * 8);
        }
        CP_COMMIT();
    }

    const __nv_bfloat16* kvs[4] = {kh, kl, vh, vl};
    auto fillkv = [&](int kt, int s) {
        uint32_t stg = sKV + s * ATT_KV_STAGE;
        size_t kvrow = (size_t)(b * SS) + (size_t)kt * 128;
        for (int i = tid; i < 4096; i += 256) {
            int t = i >> 10, idx = i & 1023, r = idx >> 3, ch = idx & 7;
            CP16(sw128(stg + t * ATT_TILE_B, r, ch),
                 kvs[t] + (kvrow + r) * DD + hoff + ch * 8);
        }
        CP_COMMIT();
    };

    fillkv(0, 0);
    if (qt >= 1) fillkv(1, 1);

    float o[8][4];
#pragma unroll
    for (int i = 0; i < 8; i++)
#pragma unroll
        for (int q = 0; q < 4; q++) o[i][q] = 0.0f;
    float mrow[2] = {-1e30f, -1e30f};
    float lrow[2] = {0.0f, 0.0f};

    uint32_t aQh[4][4], aQl[4][4];
    const int qr = lane >> 2, qc = lane & 3;

    for (int kt = 0; kt <= qt; kt++) {
        int s = kt & 1;
        if (kt + 1 <= qt) { CP_WAIT(1); } else { CP_WAIT(0); }
        __syncthreads();

        if (kt == 0) {
#pragma unroll
            for (int ks = 0; ks < 4; ks++) {
                ldsm4(aQh[ks], fa_a(sQh, w * 16, ks, lane));
                ldsm4(aQl[ks], fa_a(sQl, w * 16, ks, lane));
            }
        }

        uint32_t tKh = sKV + s * ATT_KV_STAGE;
        uint32_t tKl = tKh + ATT_TILE_B;
        uint32_t tVh = tKh + 2 * ATT_TILE_B;
        uint32_t tVl = tKh + 3 * ATT_TILE_B;

        // ---- S = Q @ K^T  (scale folded into Q) ----
        float sfr[16][4];
#pragma unroll
        for (int i = 0; i < 16; i++)
#pragma unroll
            for (int q = 0; q < 4; q++) sfr[i][q] = 0.0f;

#pragma unroll
        for (int ks = 0; ks < 4; ks++)
#pragma unroll
            for (int ng = 0; ng < 8; ng++) {
                uint32_t bh4[4], bl4[4];
                ldsm4(bh4, fa_b(tKh, ng * 16, ks, lane));
                ldsm4(bl4, fa_b(tKl, ng * 16, ks, lane));
                mma16816(sfr[2 * ng], aQh[ks], &bh4[0]);
                mma16816(sfr[2 * ng], aQh[ks], &bl4[0]);
                mma16816(sfr[2 * ng], aQl[ks], &bh4[0]);
                mma16816(sfr[2 * ng + 1], aQh[ks], &bh4[2]);
                mma16816(sfr[2 * ng + 1], aQh[ks], &bl4[2]);
                mma16816(sfr[2 * ng + 1], aQl[ks], &bh4[2]);
            }

        // ---- causal mask (diagonal tile only) ----
        if (kt == qt) {
            int r0 = w * 16 + qr;
#pragma unroll
            for (int nf = 0; nf < 16; nf++) {
                int c0 = nf * 8 + qc * 2;
                if (c0 > r0)     sfr[nf][0] = -1e30f;
                if (c0 + 1 > r0) sfr[nf][1] = -1e30f;
                if (c0 > r0 + 8)     sfr[nf][2] = -1e30f;
                if (c0 + 1 > r0 + 8) sfr[nf][3] = -1e30f;
            }
        }

        // ---- online softmax ----
        float tm0 = -1e30f, tm1 = -1e30f;
#pragma unroll
        for (int nf = 0; nf < 16; nf++) {
            tm0 = fmaxf(tm0, fmaxf(sfr[nf][0], sfr[nf][1]));
            tm1 = fmaxf(tm1, fmaxf(sfr[nf][2], sfr[nf][3]));
        }
#pragma unroll
        for (int off = 1; off <= 2; off <<= 1) {
            tm0 = fmaxf(tm0, __shfl_xor_sync(0xffffffffu, tm0, off));
            tm1 = fmaxf(tm1, __shfl_xor_sync(0xffffffffu, tm1, off));
        }
        float mn0 = fmaxf(mrow[0], tm0), mn1 = fmaxf(mrow[1], tm1);
        float al0 = __expf(mrow[0] - mn0), al1 = __expf(mrow[1] - mn1);
        mrow[0] = mn0; mrow[1] = mn1;

        float rs0 = 0.0f, rs1 = 0.0f;
#pragma unroll
        for (int nf = 0; nf < 16; nf++) {
            sfr[nf][0] = __expf(sfr[nf][0] - mn0);
            sfr[nf][1] = __expf(sfr[nf][1] - mn0);
            sfr[nf][2] = __expf(sfr[nf][2] - mn1);
            sfr[nf][3] = __expf(sfr[nf][3] - mn1);
            rs0 += sfr[nf][0] + sfr[nf][1];
            rs1 += sfr[nf][2] + sfr[nf][3];
        }
#pragma unroll
        for (int off = 1; off <= 2; off <<= 1) {
            rs0 += __shfl_xor_sync(0xffffffffu, rs0, off);
            rs1 += __shfl_xor_sync(0xffffffffu, rs1, off);
        }
        lrow[0] = lrow[0] * al0 + rs0;
        lrow[1] = lrow[1] * al1 + rs1;
#pragma unroll
        for (int i = 0; i < 8; i++) {
            o[i][0] *= al0; o[i][1] *= al0;
            o[i][2] *= al1; o[i][3] *= al1;
        }

        // ---- O += P @ V  (Ph*Vh + Pl*Vh + Ph*Vl) ----
#pragma unroll
        for (int ks = 0; ks < 8; ks++) {
            const float* f0 = sfr[2 * ks];
            const float* f1 = sfr[2 * ks + 1];
            uint32_t phx[4], plx[4];
            phx[0] = pack_bf2(f0[0], f0[1]);
            phx[1] = pack_bf2(f0[2], f0[3]);
            phx[2] = pack_bf2(f1[0], f1[1]);
            phx[3] = pack_bf2(f1[2], f1[3]);
            {
                __nv_bfloat162 h0 = *(__nv_bfloat162*)&phx[0];
                __nv_bfloat162 h1 = *(__nv_bfloat162*)&phx[1];
                __nv_bfloat162 h2 = *(__nv_bfloat162*)&phx[2];
                __nv_bfloat162 h3 = *(__nv_bfloat162*)&phx[3];
                plx[0] = pack_bf2(f0[0] - __bfloat162float(h0.x), f0[1] - __bfloat162float(h0.y));
                plx[1] = pack_bf2(f0[2] - __bfloat162float(h1.x), f0[3] - __bfloat162float(h1.y));
                plx[2] = pack_bf2(f1[0] - __bfloat162float(h2.x), f1[1] - __bfloat162float(h2.y));
                plx[3] = pack_bf2(f1[2] - __bfloat162float(h3.x), f1[3] - __bfloat162float(h3.y));
            }
#pragma unroll
            for (int ng = 0; ng < 4; ng++) {
                uint32_t vh4[4], vl4[4];
                ldsm4t(vh4, fa_v(tVh, ks * 16, ng * 16, lane));
                ldsm4t(vl4, fa_v(tVl, ks * 16, ng * 16, lane));
                mma16816(o[2 * ng],     phx, &vh4[0]);
                mma16816(o[2 * ng],     plx, &vh4[0]);
                mma16816(o[2 * ng],     phx, &vl4[0]);
                mma16816(o[2 * ng + 1], phx, &vh4[2]);
                mma16816(o[2 * ng + 1], plx, &vh4[2]);
                mma16816(o[2 * ng + 1], phx, &vl4[2]);
            }
        }

        __syncthreads();   // all warps done reading stage s
        if (kt + 2 <= qt) fillkv(kt + 2, s);
    }

    // ---- epilogue: O/l -> yh/yl ----
    float inv0 = 1.0f / lrow[0];
    float inv1 = 1.0f / lrow[1];
    size_t r0 = rowbase + w * 16 + qr;
#pragma unroll
    for (int i = 0; i < 8; i++) {
        int col = hoff + i * 8 + qc * 2;
        float x0 = o[i][0] * inv0, x1 = o[i][1] * inv0;
        float x2 = o[i][2] * inv1, x3 = o[i][3] * inv1;
        __nv_bfloat16 h0 = __float2bfloat16(x0), h1 = __float2bfloat16(x1);
        __nv_bfloat16 h2 = __float2bfloat16(x2), h3 = __float2bfloat16(x3);
        size_t i0 = r0 * DD + col;
        size_t i1 = (r0 + 8) * DD + col;
        *(__nv_bfloat162*)(yh + i0) = __halves2bfloat162(h0, h1);
        *(__nv_bfloat162*)(yh + i1) = __halves2bfloat162(h2, h3);
        *(__nv_bfloat162*)(yl + i0) = __floats2bfloat162_rn(
            x0 - __bfloat162float(h0), x1 - __bfloat162float(h1));
        *(__nv_bfloat162*)(yl + i1) = __floats2bfloat162_rn(
            x2 - __bfloat162float(h2), x3 - __bfloat162float(h3));
    }
}

// ---------------------------------------------------------------------------
extern "C" void kernel_launch(void* const* d_in, const int* in_sizes, int n_in,
                              void* d_out, int out_size)
{
    const float* x      = (const float*)d_in[0];
    const float* W_attn = (const float*)d_in[1];
    const float* b_attn = (const float*)d_in[2];
    const float* W_proj = (const float*)d_in[3];
    const float* b_proj = (const float*)d_in[4];
    float* out = (float*)d_out;

    __nv_bfloat16 *xh, *xl, *qhp, *qlp, *khp, *klp, *vhp, *vlp, *yhp, *ylp;
    __nv_bfloat16 *wah, *wal, *wph, *wpl;
    cudaGetSymbolAddress((void**)&xh,  g_xh);
    cudaGetSymbolAddress((void**)&xl,  g_xl);
    cudaGetSymbolAddress((void**)&qhp, g_qh);
    cudaGetSymbolAddress((void**)&qlp, g_ql);
    cudaGetSymbolAddress((void**)&khp, g_kh);
    cudaGetSymbolAddress((void**)&klp, g_kl);
    cudaGetSymbolAddress((void**)&vhp, g_vh);
    cudaGetSymbolAddress((void**)&vlp, g_vl);
    cudaGetSymbolAddress((void**)&yhp, g_yh);
    cudaGetSymbolAddress((void**)&ylp, g_yl);
    cudaGetSymbolAddress((void**)&wah, g_wah);
    cudaGetSymbolAddress((void**)&wal, g_wal);
    cudaGetSymbolAddress((void**)&wph, g_wph);
    cudaGetSymbolAddress((void**)&wpl, g_wpl);

    cudaFuncSetAttribute(gemm_mma_bf16x3, cudaFuncAttributeMaxDynamicSharedMemorySize,
                         (int)GEMM_SMEM);
    cudaFuncSetAttribute(flash_attn_mma, cudaFuncAttributeMaxDynamicSharedMemorySize,
                         (int)ATT_SMEM);

    // input conversions
    split_kernel<<<(MROWS * KDIM / 4 + 255) / 256, 256>>>(x, xh, xl, MROWS * KDIM / 4);
    wsplit_t<<<dim3(3 * DD / 32, KDIM / 32), dim3(32, 8)>>>(W_attn, wah, wal, KDIM, 3 * DD);
    wsplit_t<<<dim3(DD / 32, KDIM / 32), dim3(32, 8)>>>(W_proj, wph, wpl, KDIM, DD);

    // 1) qkv projection, epilogue splits straight into q/k/v hi+lo (q pre-scaled)
    gemm_mma_bf16x3<<<dim3(3 * DD / GBN, MROWS / GBM), 256, GEMM_SMEM>>>(
        xh, xl, wah, wal, b_attn, nullptr, 3 * DD, 1,
        qhp, qlp, khp, klp, vhp, vlp);

    // 2) attention (tensor-core), writes yh/yl directly
    flash_attn_mma<<<dim3(SS / 128, HH, BB), 256, ATT_SMEM>>>(
        qhp, qlp, khp, klp, vhp, vlp, yhp, ylp);

    // 3) out = y @ W_proj + b_proj (fp32 epilogue)
    gemm_mma_bf16x3<<<dim3(DD / GBN, MROWS / GBM), 256, GEMM_SMEM>>>(
        yhp, ylp, wph, wpl, b_proj, out, DD, 0,
        nullptr, nullptr, nullptr, nullptr, nullptr, nullptr);
}

// round 5
// speedup vs baseline: 2.8209x; 1.0018x over previous
#include <cuda_runtime.h>
#include <cuda_bf16.h>
#include <math.h>
#include <stdint.h>

// Problem shape (fixed by the reference)
#define BB 4
#define SS 2048
#define DD 1024
#define HH 16
#define HDIM 64
#define MROWS (BB * SS)          // 8192
#define KDIM 1024

// ---------------------------------------------------------------------------
// Scratch: device globals (no cudaMalloc allowed)
// ---------------------------------------------------------------------------
__device__ __nv_bfloat16 g_xh[(size_t)MROWS * KDIM];
__device__ __nv_bfloat16 g_xl[(size_t)MROWS * KDIM];
__device__ __nv_bfloat16 g_qh[(size_t)MROWS * DD];
__device__ __nv_bfloat16 g_ql[(size_t)MROWS * DD];
__device__ __nv_bfloat16 g_kh[(size_t)MROWS * DD];
__device__ __nv_bfloat16 g_kl[(size_t)MROWS * DD];
__device__ __nv_bfloat16 g_vh[(size_t)MROWS * DD];
__device__ __nv_bfloat16 g_vl[(size_t)MROWS * DD];
__device__ __nv_bfloat16 g_yh[(size_t)MROWS * KDIM];
__device__ __nv_bfloat16 g_yl[(size_t)MROWS * KDIM];
__device__ __nv_bfloat16 g_wah[(size_t)3 * DD * KDIM];   // W_attn^T hi/lo [N,K]
__device__ __nv_bfloat16 g_wal[(size_t)3 * DD * KDIM];
__device__ __nv_bfloat16 g_wph[(size_t)DD * KDIM];       // W_proj^T hi/lo [N,K]
__device__ __nv_bfloat16 g_wpl[(size_t)DD * KDIM];

// ---------------------------------------------------------------------------
// PTX helpers (base ISA only: cp.async / ldmatrix / mma.sync)
// ---------------------------------------------------------------------------
__device__ __forceinline__ uint32_t smem_u32(const void* p) {
    uint32_t a;
    asm("{ .reg .u64 t; cvta.to.shared.u64 t, %1; cvt.u32.u64 %0, t; }"
        : "=r"(a) : "l"(p));
    return a;
}

#define CP16(smem, gptr) \
    asm volatile("cp.async.cg.shared.global [%0], [%1], 16;" :: "r"(smem), "l"(gptr))
#define CP_COMMIT() asm volatile("cp.async.commit_group;" ::: "memory")
#define CP_WAIT(n)  asm volatile("cp.async.wait_group %0;" :: "n"(n) : "memory")

__device__ __forceinline__ void ldsm4(uint32_t* r, uint32_t addr) {
    asm volatile("ldmatrix.sync.aligned.m8n8.x4.shared.b16 {%0,%1,%2,%3}, [%4];"
                 : "=r"(r[0]), "=r"(r[1]), "=r"(r[2]), "=r"(r[3]) : "r"(addr));
}
__device__ __forceinline__ void ldsm4t(uint32_t* r, uint32_t addr) {
    asm volatile("ldmatrix.sync.aligned.m8n8.x4.trans.shared.b16 {%0,%1,%2,%3}, [%4];"
                 : "=r"(r[0]), "=r"(r[1]), "=r"(r[2]), "=r"(r[3]) : "r"(addr));
}

__device__ __forceinline__ void mma16816(float* c, const uint32_t* a, const uint32_t* b) {
    asm volatile(
        "mma.sync.aligned.m16n8k16.row.col.f32.bf16.bf16.f32 "
        "{%0,%1,%2,%3}, {%4,%5,%6,%7}, {%8,%9}, {%0,%1,%2,%3};"
        : "+f"(c[0]), "+f"(c[1]), "+f"(c[2]), "+f"(c[3])
        : "r"(a[0]), "r"(a[1]), "r"(a[2]), "r"(a[3]), "r"(b[0]), "r"(b[1]));
}

__device__ __forceinline__ uint32_t pack_bf2(float a, float b) {
    __nv_bfloat162 t = __floats2bfloat162_rn(a, b);
    return *(uint32_t*)&t;
}

// ---------------------------------------------------------------------------
// Split fp32 -> bf16 hi + bf16 lo
// ---------------------------------------------------------------------------
__global__ __launch_bounds__(256) void split_kernel(
    const float* __restrict__ in, __nv_bfloat16* __restrict__ hi,
    __nv_bfloat16* __restrict__ lo, int n4)
{
    int i = blockIdx.x * 256 + threadIdx.x;
    if (i >= n4) return;
    float4 v = ((const float4*)in)[i];
    __nv_bfloat16 h0 = __float2bfloat16(v.x), h1 = __float2bfloat16(v.y);
    __nv_bfloat16 h2 = __float2bfloat16(v.z), h3 = __float2bfloat16(v.w);
    __nv_bfloat162* hp = (__nv_bfloat162*)hi;
    __nv_bfloat162* lp = (__nv_bfloat162*)lo;
    hp[2 * i + 0] = __halves2bfloat162(h0, h1);
    hp[2 * i + 1] = __halves2bfloat162(h2, h3);
    lp[2 * i + 0] = __floats2bfloat162_rn(v.x - __bfloat162float(h0),
                                          v.y - __bfloat162float(h1));
    lp[2 * i + 1] = __floats2bfloat162_rn(v.z - __bfloat162float(h2),
                                          v.w - __bfloat162float(h3));
}

// ---------------------------------------------------------------------------
// Transpose + split: W[K,N] fp32 -> Bt_hi/Bt_lo [N,K] bf16
// ---------------------------------------------------------------------------
__global__ void wsplit_t(const float* __restrict__ W, __nv_bfloat16* __restrict__ bh,
                         __nv_bfloat16* __restrict__ bl, int Kd, int Nd)
{
    __shared__ float t[32][33];
    int k0 = blockIdx.y * 32, n0 = blockIdx.x * 32;
    int tx = threadIdx.x, ty = threadIdx.y;   // block (32, 8)
    for (int r = ty; r < 32; r += 8)
        t[r][tx] = W[(size_t)(k0 + r) * Nd + n0 + tx];
    __syncthreads();
    for (int r = ty; r < 32; r += 8) {
        float v = t[tx][r];
        __nv_bfloat16 h = __float2bfloat16(v);
        bh[(size_t)(n0 + r) * Kd + k0 + tx] = h;
        bl[(size_t)(n0 + r) * Kd + k0 + tx] = __float2bfloat16(v - __bfloat162float(h));
    }
}

// ---------------------------------------------------------------------------
// mma.sync bf16x3 GEMM with product-major MMA ordering (dep distance 16).
//   mode 0: C = acc + bias (fp32)
//   mode 1: split-write into q/k/v hi+lo bf16 arrays (q scaled by 0.125)
// ---------------------------------------------------------------------------
#define GBM 128
#define GBN 128
#define GBK 32
#define TILE_BYTES (64 * 128)
#define STAGE_BYTES (4 * TILE_BYTES)
#define NSTAGE 3
#define GEMM_SMEM (NSTAGE * STAGE_BYTES)

__device__ __forceinline__ uint32_t a_addr(uint32_t tb, int m0, int ks, int lane) {
    int row = m0 + (lane & 15);
    int p = row >> 1;
    int chl = ((row & 1) << 2) | (ks << 1) | (lane >> 4);
    return tb + p * 128 + ((chl ^ (p & 7)) << 4);
}
__device__ __forceinline__ uint32_t b_addr(uint32_t tb, int n0, int ks, int lane) {
    int row = n0 + (lane & 7) + ((lane >> 4) << 3);
    int p = row >> 1;
    int chl = ((row & 1) << 2) | (ks << 1) | ((lane >> 3) & 1);
    return tb + p * 128 + ((chl ^ (p & 7)) << 4);
}

__global__ __launch_bounds__(256, 1) void gemm_mma_bf16x3(
    const __nv_bfloat16* __restrict__ Ah, const __nv_bfloat16* __restrict__ Al,
    const __nv_bfloat16* __restrict__ Bh, const __nv_bfloat16* __restrict__ Bl,
    const float* __restrict__ bias, float* __restrict__ C, int Nld, int mode,
    __nv_bfloat16* __restrict__ oqh, __nv_bfloat16* __restrict__ oql,
    __nv_bfloat16* __restrict__ okh, __nv_bfloat16* __restrict__ okl,
    __nv_bfloat16* __restrict__ ovh, __nv_bfloat16* __restrict__ ovl)
{
    extern __shared__ __align__(1024) char smraw[];
    const uint32_t sbase = smem_u32(smraw);
    const int tid = threadIdx.x;
    const int lane = tid & 31;
    const int wid = tid >> 5;
    const int wm = wid & 1;
    const int wn = wid >> 1;
    const int row0 = blockIdx.y * GBM;
    const int col0 = blockIdx.x * GBN;

    const __nv_bfloat16* srcs[4];
    srcs[0] = Ah + (size_t)row0 * KDIM;
    srcs[1] = Al + (size_t)row0 * KDIM;
    srcs[2] = Bh + (size_t)col0 * KDIM;
    srcs[3] = Bl + (size_t)col0 * KDIM;

    float acc[4][4][4];
#pragma unroll
    for (int mi = 0; mi < 4; mi++)
#pragma unroll
        for (int ni = 0; ni < 4; ni++)
#pragma unroll
            for (int q = 0; q < 4; q++) acc[mi][ni][q] = 0.0f;

    auto fill = [&](int c, int s) {
        uint32_t stg = sbase + s * STAGE_BYTES;
#pragma unroll
        for (int t = 0; t < 4; t++) {
            uint32_t tb = stg + t * TILE_BYTES;
            const __nv_bfloat16* src = srcs[t] + c * GBK;
#pragma unroll
            for (int ii = 0; ii < 2; ii++) {
                int i = tid + ii * 256;
                int row = i >> 2, kc = i & 3;
                int p = row >> 1;
                int ch = (((row & 1) << 2) | kc) ^ (p & 7);
                CP16(tb + p * 128 + ch * 16, src + (size_t)row * KDIM + kc * 8);
            }
        }
        CP_COMMIT();
    };

    fill(0, 0);
    fill(1, 1);

    const int NCH = KDIM / GBK;   // 32
    for (int c = 0; c < NCH; c++) {
        int s = c % 3;
        if (c + 2 < NCH) { CP_WAIT(1); } else { CP_WAIT(0); }
        __syncthreads();
        if (c + 2 < NCH) fill(c + 2, (c + 2) % 3);

        uint32_t st = sbase + s * STAGE_BYTES;
#pragma unroll
        for (int ks = 0; ks < 2; ks++) {
            uint32_t aHf[4][4], aLf[4][4], bHf[2][4], bLf[2][4];
#pragma unroll
            for (int mi = 0; mi < 4; mi++) {
                ldsm4(aHf[mi], a_addr(st,              wm * 64 + mi * 16, ks, lane));
                ldsm4(aLf[mi], a_addr(st + TILE_BYTES, wm * 64 + mi * 16, ks, lane));
            }
#pragma unroll
            for (int g = 0; g < 2; g++) {
                ldsm4(bHf[g], b_addr(st + 2 * TILE_BYTES, wn * 32 + g * 16, ks, lane));
                ldsm4(bLf[g], b_addr(st + 3 * TILE_BYTES, wn * 32 + g * 16, ks, lane));
            }
            // product-major ordering: same-acc dependency distance = 16 MMAs
#pragma unroll
            for (int mi = 0; mi < 4; mi++)
#pragma unroll
                for (int ni = 0; ni < 4; ni++)
                    mma16816(acc[mi][ni], aHf[mi], &bHf[ni >> 1][(ni & 1) * 2]);
#pragma unroll
            for (int mi = 0; mi < 4; mi++)
#pragma unroll
                for (int ni = 0; ni < 4; ni++)
                    mma16816(acc[mi][ni], aHf[mi], &bLf[ni >> 1][(ni & 1) * 2]);
#pragma unroll
            for (int mi = 0; mi < 4; mi++)
#pragma unroll
                for (int ni = 0; ni < 4; ni++)
                    mma16816(acc[mi][ni], aLf[mi], &bHf[ni >> 1][(ni & 1) * 2]);
        }
    }

    const int qr = lane >> 2, qc = lane & 3;
    if (mode == 0) {
#pragma unroll
        for (int mi = 0; mi < 4; mi++)
#pragma unroll
            for (int ni = 0; ni < 4; ni++) {
                int row = row0 + wm * 64 + mi * 16 + qr;
                int col = col0 + wn * 32 + ni * 8 + qc * 2;
                float2 bv = *(const float2*)(bias + col);
                float2 v0, v1;
                v0.x = acc[mi][ni][0] + bv.x;  v0.y = acc[mi][ni][1] + bv.y;
                v1.x = acc[mi][ni][2] + bv.x;  v1.y = acc[mi][ni][3] + bv.y;
                *(float2*)(C + (size_t)row * Nld + col) = v0;
                *(float2*)(C + (size_t)(row + 8) * Nld + col) = v1;
            }
    } else {
        int t = col0 >> 10;
        __nv_bfloat16* oh = (t == 0) ? oqh : (t == 1) ? okh : ovh;
        __nv_bfloat16* ol = (t == 0) ? oql : (t == 1) ? okl : ovl;
        float sc = (t == 0) ? 0.125f : 1.0f;
#pragma unroll
        for (int mi = 0; mi < 4; mi++)
#pragma unroll
            for (int ni = 0; ni < 4; ni++) {
                int row = row0 + wm * 64 + mi * 16 + qr;
                int gcol = col0 + wn * 32 + ni * 8 + qc * 2;
                int lcol = gcol & 1023;
                float2 bv = *(const float2*)(bias + gcol);
                float x0 = (acc[mi][ni][0] + bv.x) * sc;
                float x1 = (acc[mi][ni][1] + bv.y) * sc;
                float x2 = (acc[mi][ni][2] + bv.x) * sc;
                float x3 = (acc[mi][ni][3] + bv.y) * sc;
                __nv_bfloat16 h0 = __float2bfloat16(x0), h1 = __float2bfloat16(x1);
                __nv_bfloat16 h2 = __float2bfloat16(x2), h3 = __float2bfloat16(x3);
                size_t i0 = (size_t)row * DD + lcol;
                size_t i1 = (size_t)(row + 8) * DD + lcol;
                *(__nv_bfloat162*)(oh + i0) = __halves2bfloat162(h0, h1);
                *(__nv_bfloat162*)(oh + i1) = __halves2bfloat162(h2, h3);
                *(__nv_bfloat162*)(ol + i0) = __floats2bfloat162_rn(
                    x0 - __bfloat162float(h0), x1 - __bfloat162float(h1));
                *(__nv_bfloat162*)(ol + i1) = __floats2bfloat162_rn(
                    x2 - __bfloat162float(h2), x3 - __bfloat162float(h3));
            }
    }
}

// ---------------------------------------------------------------------------
// Flash attention with mma.sync, bf16x3, causal; product-paired MMA ordering.
// ---------------------------------------------------------------------------
#define ATT_TILE_B 16384
#define ATT_KV_STAGE (4 * ATT_TILE_B)
#define ATT_SMEM (2 * ATT_TILE_B + 2 * ATT_KV_STAGE)   // 163840

__device__ __forceinline__ uint32_t sw128(uint32_t tb, int row, int chunk) {
    return tb + row * 128 + ((chunk ^ (row & 7)) << 4);
}
__device__ __forceinline__ uint32_t fa_a(uint32_t tb, int m0, int ks, int lane) {
    int row = m0 + (lane & 15);
    return sw128(tb, row, ks * 2 + (lane >> 4));
}
__device__ __forceinline__ uint32_t fa_b(uint32_t tb, int n0, int ks, int lane) {
    int row = n0 + (lane & 7) + ((lane >> 4) << 3);
    return sw128(tb, row, ks * 2 + ((lane >> 3) & 1));
}
__device__ __forceinline__ uint32_t fa_v(uint32_t tb, int kv0, int hd0, int lane) {
    int row = kv0 + (((lane >> 3) & 1) << 3) + (lane & 7);
    return sw128(tb, row, (hd0 >> 3) + (lane >> 4));
}

__global__ __launch_bounds__(256, 1) void flash_attn_mma(
    const __nv_bfloat16* __restrict__ qh, const __nv_bfloat16* __restrict__ ql,
    const __nv_bfloat16* __restrict__ kh, const __nv_bfloat16* __restrict__ kl,
    const __nv_bfloat16* __restrict__ vh, const __nv_bfloat16* __restrict__ vl,
    __nv_bfloat16* __restrict__ yh, __nv_bfloat16* __restrict__ yl)
{
    extern __shared__ __align__(1024) char smraw[];
    const uint32_t sb = smem_u32(smraw);
    const int qt = blockIdx.x, h = blockIdx.y, b = blockIdx.z;
    const int tid = threadIdx.x, lane = tid & 31, w = tid >> 5;
    const size_t rowbase = (size_t)(b * SS) + qt * 128;
    const int hoff = h * HDIM;

    const uint32_t sQh = sb, sQl = sb + ATT_TILE_B;
    const uint32_t sKV = sb + 2 * ATT_TILE_B;

    {
        const __nv_bfloat16* qs[2] = {qh, ql};
        for (int i = tid; i < 2048; i += 256) {
            int t = i >> 10, idx = i & 1023, r = idx >> 3, ch = idx & 7;
            CP16(sw128(t ? sQl : sQh, r, ch),
                 qs[t] + (rowbase + r) * DD + hoff + ch * 8);
        }
        CP_COMMIT();
    }

    const __nv_bfloat16* kvs[4] = {kh, kl, vh, vl};
    auto fillkv = [&](int kt, int s) {
        uint32_t stg = sKV + s * ATT_KV_STAGE;
        size_t kvrow = (size_t)(b * SS) + (size_t)kt * 128;
        for (int i = tid; i < 4096; i += 256) {
            int t = i >> 10, idx = i & 1023, r = idx >> 3, ch = idx & 7;
            CP16(sw128(stg + t * ATT_TILE_B, r, ch),
                 kvs[t] + (kvrow + r) * DD + hoff + ch * 8);
        }
        CP_COMMIT();
    };

    fillkv(0, 0);
    if (qt >= 1) fillkv(1, 1);

    float o[8][4];
#pragma unroll
    for (int i = 0; i < 8; i++)
#pragma unroll
        for (int q = 0; q < 4; q++) o[i][q] = 0.0f;
    float mrow[2] = {-1e30f, -1e30f};
    float lrow[2] = {0.0f, 0.0f};

    uint32_t aQh[4][4], aQl[4][4];
    const int qr = lane >> 2, qc = lane & 3;

    for (int kt = 0; kt <= qt; kt++) {
        int s = kt & 1;
        if (kt + 1 <= qt) { CP_WAIT(1); } else { CP_WAIT(0); }
        __syncthreads();

        if (kt == 0) {
#pragma unroll
            for (int ks = 0; ks < 4; ks++) {
                ldsm4(aQh[ks], fa_a(sQh, w * 16, ks, lane));
                ldsm4(aQl[ks], fa_a(sQl, w * 16, ks, lane));
            }
        }

        uint32_t tKh = sKV + s * ATT_KV_STAGE;
        uint32_t tKl = tKh + ATT_TILE_B;
        uint32_t tVh = tKh + 2 * ATT_TILE_B;
        uint32_t tVl = tKh + 3 * ATT_TILE_B;

        // ---- S = Q @ K^T, pair n-tiles: dep distance 4 ----
        float sfr[16][4];
#pragma unroll
        for (int i = 0; i < 16; i++)
#pragma unroll
            for (int q = 0; q < 4; q++) sfr[i][q] = 0.0f;

#pragma unroll
        for (int ks = 0; ks < 4; ks++)
#pragma unroll
            for (int np = 0; np < 4; np++) {
                int ng0 = 2 * np, ng1 = 2 * np + 1;
                uint32_t bhA[4], blA[4], bhB[4], blB[4];
                ldsm4(bhA, fa_b(tKh, ng0 * 16, ks, lane));
                ldsm4(blA, fa_b(tKl, ng0 * 16, ks, lane));
                ldsm4(bhB, fa_b(tKh, ng1 * 16, ks, lane));
                ldsm4(blB, fa_b(tKl, ng1 * 16, ks, lane));
                // HH
                mma16816(sfr[2 * ng0],     aQh[ks], &bhA[0]);
                mma16816(sfr[2 * ng0 + 1], aQh[ks], &bhA[2]);
                mma16816(sfr[2 * ng1],     aQh[ks], &bhB[0]);
                mma16816(sfr[2 * ng1 + 1], aQh[ks], &bhB[2]);
                // HL
                mma16816(sfr[2 * ng0],     aQh[ks], &blA[0]);
                mma16816(sfr[2 * ng0 + 1], aQh[ks], &blA[2]);
                mma16816(sfr[2 * ng1],     aQh[ks], &blB[0]);
                mma16816(sfr[2 * ng1 + 1], aQh[ks], &blB[2]);
                // LH
                mma16816(sfr[2 * ng0],     aQl[ks], &bhA[0]);
                mma16816(sfr[2 * ng0 + 1], aQl[ks], &bhA[2]);
                mma16816(sfr[2 * ng1],     aQl[ks], &bhB[0]);
                mma16816(sfr[2 * ng1 + 1], aQl[ks], &bhB[2]);
            }

        // ---- causal mask (diagonal tile only) ----
        if (kt == qt) {
            int r0 = w * 16 + qr;
#pragma unroll
            for (int nf = 0; nf < 16; nf++) {
                int c0 = nf * 8 + qc * 2;
                if (c0 > r0)     sfr[nf][0] = -1e30f;
                if (c0 + 1 > r0) sfr[nf][1] = -1e30f;
                if (c0 > r0 + 8)     sfr[nf][2] = -1e30f;
                if (c0 + 1 > r0 + 8) sfr[nf][3] = -1e30f;
            }
        }

        // ---- online softmax ----
        float tm0 = -1e30f, tm1 = -1e30f;
#pragma unroll
        for (int nf = 0; nf < 16; nf++) {
            tm0 = fmaxf(tm0, fmaxf(sfr[nf][0], sfr[nf][1]));
            tm1 = fmaxf(tm1, fmaxf(sfr[nf][2], sfr[nf][3]));
        }
#pragma unroll
        for (int off = 1; off <= 2; off <<= 1) {
            tm0 = fmaxf(tm0, __shfl_xor_sync(0xffffffffu, tm0, off));
            tm1 = fmaxf(tm1, __shfl_xor_sync(0xffffffffu, tm1, off));
        }
        float mn0 = fmaxf(mrow[0], tm0), mn1 = fmaxf(mrow[1], tm1);
        float al0 = __expf(mrow[0] - mn0), al1 = __expf(mrow[1] - mn1);
        mrow[0] = mn0; mrow[1] = mn1;

        float rs0 = 0.0f, rs1 = 0.0f;
#pragma unroll
        for (int nf = 0; nf < 16; nf++) {
            sfr[nf][0] = __expf(sfr[nf][0] - mn0);
            sfr[nf][1] = __expf(sfr[nf][1] - mn0);
            sfr[nf][2] = __expf(sfr[nf][2] - mn1);
            sfr[nf][3] = __expf(sfr[nf][3] - mn1);
            rs0 += sfr[nf][0] + sfr[nf][1];
            rs1 += sfr[nf][2] + sfr[nf][3];
        }
#pragma unroll
        for (int off = 1; off <= 2; off <<= 1) {
            rs0 += __shfl_xor_sync(0xffffffffu, rs0, off);
            rs1 += __shfl_xor_sync(0xffffffffu, rs1, off);
        }
        lrow[0] = lrow[0] * al0 + rs0;
        lrow[1] = lrow[1] * al1 + rs1;
#pragma unroll
        for (int i = 0; i < 8; i++) {
            o[i][0] *= al0; o[i][1] *= al0;
            o[i][2] *= al1; o[i][3] *= al1;
        }

        // ---- O += P @ V, pair n-tiles: dep distance 4 ----
#pragma unroll
        for (int ks = 0; ks < 8; ks++) {
            const float* f0 = sfr[2 * ks];
            const float* f1 = sfr[2 * ks + 1];
            uint32_t phx[4], plx[4];
            phx[0] = pack_bf2(f0[0], f0[1]);
            phx[1] = pack_bf2(f0[2], f0[3]);
            phx[2] = pack_bf2(f1[0], f1[1]);
            phx[3] = pack_bf2(f1[2], f1[3]);
            {
                __nv_bfloat162 h0 = *(__nv_bfloat162*)&phx[0];
                __nv_bfloat162 h1 = *(__nv_bfloat162*)&phx[1];
                __nv_bfloat162 h2 = *(__nv_bfloat162*)&phx[2];
                __nv_bfloat162 h3 = *(__nv_bfloat162*)&phx[3];
                plx[0] = pack_bf2(f0[0] - __bfloat162float(h0.x), f0[1] - __bfloat162float(h0.y));
                plx[1] = pack_bf2(f0[2] - __bfloat162float(h1.x), f0[3] - __bfloat162float(h1.y));
                plx[2] = pack_bf2(f1[0] - __bfloat162float(h2.x), f1[1] - __bfloat162float(h2.y));
                plx[3] = pack_bf2(f1[2] - __bfloat162float(h3.x), f1[3] - __bfloat162float(h3.y));
            }
#pragma unroll
            for (int gp = 0; gp < 2; gp++) {
                int ng0 = 2 * gp, ng1 = 2 * gp + 1;
                uint32_t vhA[4], vlA[4], vhB[4], vlB[4];
                ldsm4t(vhA, fa_v(tVh, ks * 16, ng0 * 16, lane));
                ldsm4t(vlA, fa_v(tVl, ks * 16, ng0 * 16, lane));
                ldsm4t(vhB, fa_v(tVh, ks * 16, ng1 * 16, lane));
                ldsm4t(vlB, fa_v(tVl, ks * 16, ng1 * 16, lane));
                // Ph*Vh
                mma16816(o[2 * ng0],     phx, &vhA[0]);
                mma16816(o[2 * ng0 + 1], phx, &vhA[2]);
                mma16816(o[2 * ng1],     phx, &vhB[0]);
                mma16816(o[2 * ng1 + 1], phx, &vhB[2]);
                // Pl*Vh
                mma16816(o[2 * ng0],     plx, &vhA[0]);
                mma16816(o[2 * ng0 + 1], plx, &vhA[2]);
                mma16816(o[2 * ng1],     plx, &vhB[0]);
                mma16816(o[2 * ng1 + 1], plx, &vhB[2]);
                // Ph*Vl
                mma16816(o[2 * ng0],     phx, &vlA[0]);
                mma16816(o[2 * ng0 + 1], phx, &vlA[2]);
                mma16816(o[2 * ng1],     phx, &vlB[0]);
                mma16816(o[2 * ng1 + 1], phx, &vlB[2]);
            }
        }

        __syncthreads();
        if (kt + 2 <= qt) fillkv(kt + 2, s);
    }

    // ---- epilogue: O/l -> yh/yl ----
    float inv0 = 1.0f / lrow[0];
    float inv1 = 1.0f / lrow[1];
    size_t r0 = rowbase + w * 16 + qr;
#pragma unroll
    for (int i = 0; i < 8; i++) {
        int col = hoff + i * 8 + qc * 2;
        float x0 = o[i][0] * inv0, x1 = o[i][1] * inv0;
        float x2 = o[i][2] * inv1, x3 = o[i][3] * inv1;
        __nv_bfloat16 h0 = __float2bfloat16(x0), h1 = __float2bfloat16(x1);
        __nv_bfloat16 h2 = __float2bfloat16(x2), h3 = __float2bfloat16(x3);
        size_t i0 = r0 * DD + col;
        size_t i1 = (r0 + 8) * DD + col;
        *(__nv_bfloat162*)(yh + i0) = __halves2bfloat162(h0, h1);
        *(__nv_bfloat162*)(yh + i1) = __halves2bfloat162(h2, h3);
        *(__nv_bfloat162*)(yl + i0) = __floats2bfloat162_rn(
            x0 - __bfloat162float(h0), x1 - __bfloat162float(h1));
        *(__nv_bfloat162*)(yl + i1) = __floats2bfloat162_rn(
            x2 - __bfloat162float(h2), x3 - __bfloat162float(h3));
    }
}

// ---------------------------------------------------------------------------
extern "C" void kernel_launch(void* const* d_in, const int* in_sizes, int n_in,
                              void* d_out, int out_size)
{
    const float* x      = (const float*)d_in[0];
    const float* W_attn = (const float*)d_in[1];
    const float* b_attn = (const float*)d_in[2];
    const float* W_proj = (const float*)d_in[3];
    const float* b_proj = (const float*)d_in[4];
    float* out = (float*)d_out;

    __nv_bfloat16 *xh, *xl, *qhp, *qlp, *khp, *klp, *vhp, *vlp, *yhp, *ylp;
    __nv_bfloat16 *wah, *wal, *wph, *wpl;
    cudaGetSymbolAddress((void**)&xh,  g_xh);
    cudaGetSymbolAddress((void**)&xl,  g_xl);
    cudaGetSymbolAddress((void**)&qhp, g_qh);
    cudaGetSymbolAddress((void**)&qlp, g_ql);
    cudaGetSymbolAddress((void**)&khp, g_kh);
    cudaGetSymbolAddress((void**)&klp, g_kl);
    cudaGetSymbolAddress((void**)&vhp, g_vh);
    cudaGetSymbolAddress((void**)&vlp, g_vl);
    cudaGetSymbolAddress((void**)&yhp, g_yh);
    cudaGetSymbolAddress((void**)&ylp, g_yl);
    cudaGetSymbolAddress((void**)&wah, g_wah);
    cudaGetSymbolAddress((void**)&wal, g_wal);
    cudaGetSymbolAddress((void**)&wph, g_wph);
    cudaGetSymbolAddress((void**)&wpl, g_wpl);

    cudaFuncSetAttribute(gemm_mma_bf16x3, cudaFuncAttributeMaxDynamicSharedMemorySize,
                         (int)GEMM_SMEM);
    cudaFuncSetAttribute(flash_attn_mma, cudaFuncAttributeMaxDynamicSharedMemorySize,
                         (int)ATT_SMEM);

    split_kernel<<<(MROWS * KDIM / 4 + 255) / 256, 256>>>(x, xh, xl, MROWS * KDIM / 4);
    wsplit_t<<<dim3(3 * DD / 32, KDIM / 32), dim3(32, 8)>>>(W_attn, wah, wal, KDIM, 3 * DD);
    wsplit_t<<<dim3(DD / 32, KDIM / 32), dim3(32, 8)>>>(W_proj, wph, wpl, KDIM, DD);

    gemm_mma_bf16x3<<<dim3(3 * DD / GBN, MROWS / GBM), 256, GEMM_SMEM>>>(
        xh, xl, wah, wal, b_attn, nullptr, 3 * DD, 1,
        qhp, qlp, khp, klp, vhp, vlp);

    flash_attn_mma<<<dim3(SS / 128, HH, BB), 256, ATT_SMEM>>>(
        qhp, qlp, khp, klp, vhp, vlp, yhp, ylp);

    gemm_mma_bf16x3<<<dim3(DD / GBN, MROWS / GBM), 256, GEMM_SMEM>>>(
        yhp, ylp, wph, wpl, b_proj, out, DD, 0,
        nullptr, nullptr, nullptr, nullptr, nullptr, nullptr);
}

// round 6
// speedup vs baseline: 3.1507x; 1.1169x over previous
#include <cuda_runtime.h>
#include <cuda_bf16.h>
#include <math.h>
#include <stdint.h>

// Problem shape (fixed by the reference)
#define BB 4
#define SS 2048
#define DD 1024
#define HH 16
#define HDIM 64
#define MROWS (BB * SS)          // 8192
#define KDIM 1024

// ---------------------------------------------------------------------------
// Scratch: device globals (no cudaMalloc allowed)
// ---------------------------------------------------------------------------
__device__ __nv_bfloat16 g_xh[(size_t)MROWS * KDIM];
__device__ __nv_bfloat16 g_xl[(size_t)MROWS * KDIM];
__device__ __nv_bfloat16 g_qh[(size_t)MROWS * DD];
__device__ __nv_bfloat16 g_ql[(size_t)MROWS * DD];
__device__ __nv_bfloat16 g_kh[(size_t)MROWS * DD];
__device__ __nv_bfloat16 g_kl[(size_t)MROWS * DD];
__device__ __nv_bfloat16 g_vh[(size_t)MROWS * DD];
__device__ __nv_bfloat16 g_vl[(size_t)MROWS * DD];
__device__ __nv_bfloat16 g_yh[(size_t)MROWS * KDIM];
__device__ __nv_bfloat16 g_yl[(size_t)MROWS * KDIM];
__device__ __nv_bfloat16 g_wah[(size_t)3 * DD * KDIM];   // W_attn^T hi/lo [N,K]
__device__ __nv_bfloat16 g_wal[(size_t)3 * DD * KDIM];
__device__ __nv_bfloat16 g_wph[(size_t)DD * KDIM];       // W_proj^T hi/lo [N,K]
__device__ __nv_bfloat16 g_wpl[(size_t)DD * KDIM];

// ---------------------------------------------------------------------------
// PTX helpers (base ISA only: cp.async / ldmatrix / mma.sync)
// ---------------------------------------------------------------------------
__device__ __forceinline__ uint32_t smem_u32(const void* p) {
    uint32_t a;
    asm("{ .reg .u64 t; cvta.to.shared.u64 t, %1; cvt.u32.u64 %0, t; }"
        : "=r"(a) : "l"(p));
    return a;
}

#define CP16(smem, gptr) \
    asm volatile("cp.async.cg.shared.global [%0], [%1], 16;" :: "r"(smem), "l"(gptr))
#define CP_COMMIT() asm volatile("cp.async.commit_group;" ::: "memory")
#define CP_WAIT(n)  asm volatile("cp.async.wait_group %0;" :: "n"(n) : "memory")

__device__ __forceinline__ void ldsm4(uint32_t* r, uint32_t addr) {
    asm volatile("ldmatrix.sync.aligned.m8n8.x4.shared.b16 {%0,%1,%2,%3}, [%4];"
                 : "=r"(r[0]), "=r"(r[1]), "=r"(r[2]), "=r"(r[3]) : "r"(addr));
}
__device__ __forceinline__ void ldsm4t(uint32_t* r, uint32_t addr) {
    asm volatile("ldmatrix.sync.aligned.m8n8.x4.trans.shared.b16 {%0,%1,%2,%3}, [%4];"
                 : "=r"(r[0]), "=r"(r[1]), "=r"(r[2]), "=r"(r[3]) : "r"(addr));
}

__device__ __forceinline__ void mma16816(float* c, const uint32_t* a, const uint32_t* b) {
    asm volatile(
        "mma.sync.aligned.m16n8k16.row.col.f32.bf16.bf16.f32 "
        "{%0,%1,%2,%3}, {%4,%5,%6,%7}, {%8,%9}, {%0,%1,%2,%3};"
        : "+f"(c[0]), "+f"(c[1]), "+f"(c[2]), "+f"(c[3])
        : "r"(a[0]), "r"(a[1]), "r"(a[2]), "r"(a[3]), "r"(b[0]), "r"(b[1]));
}

__device__ __forceinline__ uint32_t pack_bf2(float a, float b) {
    __nv_bfloat162 t = __floats2bfloat162_rn(a, b);
    return *(uint32_t*)&t;
}

// ---------------------------------------------------------------------------
// Split fp32 -> bf16 hi + bf16 lo
// ---------------------------------------------------------------------------
__global__ __launch_bounds__(256) void split_kernel(
    const float* __restrict__ in, __nv_bfloat16* __restrict__ hi,
    __nv_bfloat16* __restrict__ lo, int n4)
{
    int i = blockIdx.x * 256 + threadIdx.x;
    if (i >= n4) return;
    float4 v = ((const float4*)in)[i];
    __nv_bfloat16 h0 = __float2bfloat16(v.x), h1 = __float2bfloat16(v.y);
    __nv_bfloat16 h2 = __float2bfloat16(v.z), h3 = __float2bfloat16(v.w);
    __nv_bfloat162* hp = (__nv_bfloat162*)hi;
    __nv_bfloat162* lp = (__nv_bfloat162*)lo;
    hp[2 * i + 0] = __halves2bfloat162(h0, h1);
    hp[2 * i + 1] = __halves2bfloat162(h2, h3);
    lp[2 * i + 0] = __floats2bfloat162_rn(v.x - __bfloat162float(h0),
                                          v.y - __bfloat162float(h1));
    lp[2 * i + 1] = __floats2bfloat162_rn(v.z - __bfloat162float(h2),
                                          v.w - __bfloat162float(h3));
}

// ---------------------------------------------------------------------------
// Transpose + split: W[K,N] fp32 -> Bt_hi/Bt_lo [N,K] bf16
// ---------------------------------------------------------------------------
__global__ void wsplit_t(const float* __restrict__ W, __nv_bfloat16* __restrict__ bh,
                         __nv_bfloat16* __restrict__ bl, int Kd, int Nd)
{
    __shared__ float t[32][33];
    int k0 = blockIdx.y * 32, n0 = blockIdx.x * 32;
    int tx = threadIdx.x, ty = threadIdx.y;   // block (32, 8)
    for (int r = ty; r < 32; r += 8)
        t[r][tx] = W[(size_t)(k0 + r) * Nd + n0 + tx];
    __syncthreads();
    for (int r = ty; r < 32; r += 8) {
        float v = t[tx][r];
        __nv_bfloat16 h = __float2bfloat16(v);
        bh[(size_t)(n0 + r) * Kd + k0 + tx] = h;
        bl[(size_t)(n0 + r) * Kd + k0 + tx] = __float2bfloat16(v - __bfloat162float(h));
    }
}

// ---------------------------------------------------------------------------
// mma.sync bf16x3 GEMM, register-dieted for 2 CTAs/SM.
//   mode 0: C = acc + bias (fp32)
//   mode 1: split-write into q/k/v hi+lo bf16 arrays (q scaled by 0.125)
// ---------------------------------------------------------------------------
#define GBM 128
#define GBN 128
#define GBK 32
#define TILE_BYTES (64 * 128)
#define STAGE_BYTES (4 * TILE_BYTES)
#define NSTAGE 3
#define GEMM_SMEM (NSTAGE * STAGE_BYTES)     // 98304

__device__ __forceinline__ uint32_t a_addr(uint32_t tb, int m0, int ks, int lane) {
    int row = m0 + (lane & 15);
    int p = row >> 1;
    int chl = ((row & 1) << 2) | (ks << 1) | (lane >> 4);
    return tb + p * 128 + ((chl ^ (p & 7)) << 4);
}
__device__ __forceinline__ uint32_t b_addr(uint32_t tb, int n0, int ks, int lane) {
    int row = n0 + (lane & 7) + ((lane >> 4) << 3);
    int p = row >> 1;
    int chl = ((row & 1) << 2) | (ks << 1) | ((lane >> 3) & 1);
    return tb + p * 128 + ((chl ^ (p & 7)) << 4);
}

__global__ __launch_bounds__(256, 2) void gemm_mma_bf16x3(
    const __nv_bfloat16* __restrict__ Ah, const __nv_bfloat16* __restrict__ Al,
    const __nv_bfloat16* __restrict__ Bh, const __nv_bfloat16* __restrict__ Bl,
    const float* __restrict__ bias, float* __restrict__ C, int Nld, int mode,
    __nv_bfloat16* __restrict__ oqh, __nv_bfloat16* __restrict__ oql,
    __nv_bfloat16* __restrict__ okh, __nv_bfloat16* __restrict__ okl,
    __nv_bfloat16* __restrict__ ovh, __nv_bfloat16* __restrict__ ovl)
{
    extern __shared__ __align__(1024) char smraw[];
    const uint32_t sbase = smem_u32(smraw);
    const int tid = threadIdx.x;
    const int lane = tid & 31;
    const int wid = tid >> 5;
    const int wm = wid & 1;
    const int wn = wid >> 1;
    const int row0 = blockIdx.y * GBM;
    const int col0 = blockIdx.x * GBN;

    // fill: thread covers rows (tid>>2) and (tid>>2)+64, k-chunk (tid&3)*8
    const int frow = tid >> 2;
    const int fkc  = tid & 3;
    uint32_t so0, so1;
    {
        int p0 = frow >> 1;
        int c0 = (((frow & 1) << 2) | fkc) ^ (p0 & 7);
        so0 = (uint32_t)(p0 * 128 + c0 * 16);
        int r1 = frow + 64;
        int p1 = r1 >> 1;
        int c1 = (((r1 & 1) << 2) | fkc) ^ (p1 & 7);
        so1 = (uint32_t)(p1 * 128 + c1 * 16);
    }
    // running source pointers (advance GBK per fill)
    const __nv_bfloat16* fs0 = Ah + (size_t)(row0 + frow) * KDIM + fkc * 8;
    const __nv_bfloat16* fs1 = Al + (size_t)(row0 + frow) * KDIM + fkc * 8;
    const __nv_bfloat16* fs2 = Bh + (size_t)(col0 + frow) * KDIM + fkc * 8;
    const __nv_bfloat16* fs3 = Bl + (size_t)(col0 + frow) * KDIM + fkc * 8;
    const size_t rstep = (size_t)64 * KDIM;

    float acc[4][4][4];
#pragma unroll
    for (int mi = 0; mi < 4; mi++)
#pragma unroll
        for (int ni = 0; ni < 4; ni++)
#pragma unroll
            for (int q = 0; q < 4; q++) acc[mi][ni][q] = 0.0f;

    auto fill = [&](int s) {
        uint32_t stg = sbase + s * STAGE_BYTES;
        CP16(stg + so0, fs0);                  CP16(stg + so1, fs0 + rstep);
        CP16(stg + TILE_BYTES + so0, fs1);     CP16(stg + TILE_BYTES + so1, fs1 + rstep);
        CP16(stg + 2 * TILE_BYTES + so0, fs2); CP16(stg + 2 * TILE_BYTES + so1, fs2 + rstep);
        CP16(stg + 3 * TILE_BYTES + so0, fs3); CP16(stg + 3 * TILE_BYTES + so1, fs3 + rstep);
        fs0 += GBK; fs1 += GBK; fs2 += GBK; fs3 += GBK;
        CP_COMMIT();
    };

    fill(0);
    fill(1);

    const int NCH = KDIM / GBK;   // 32
    for (int c = 0; c < NCH; c++) {
        int s = c % 3;
        if (c + 2 < NCH) { CP_WAIT(1); } else { CP_WAIT(0); }
        __syncthreads();
        if (c + 2 < NCH) fill((c + 2) % 3);

        uint32_t st = sbase + s * STAGE_BYTES;
#pragma unroll
        for (int ks = 0; ks < 2; ks++) {
            uint32_t aH[4][4], aL[4][4];
#pragma unroll
            for (int mi = 0; mi < 4; mi++) {
                ldsm4(aH[mi], a_addr(st,              wm * 64 + mi * 16, ks, lane));
                ldsm4(aL[mi], a_addr(st + TILE_BYTES, wm * 64 + mi * 16, ks, lane));
            }
            // process B n-groups sequentially: only 8 B regs live at a time
#pragma unroll
            for (int g = 0; g < 2; g++) {
                uint32_t bh[4], bl[4];
                ldsm4(bh, b_addr(st + 2 * TILE_BYTES, wn * 32 + g * 16, ks, lane));
                ldsm4(bl, b_addr(st + 3 * TILE_BYTES, wn * 32 + g * 16, ks, lane));
#pragma unroll
                for (int mi = 0; mi < 4; mi++) {
                    mma16816(acc[mi][2 * g],     aH[mi], &bh[0]);
                    mma16816(acc[mi][2 * g + 1], aH[mi], &bh[2]);
                }
#pragma unroll
                for (int mi = 0; mi < 4; mi++) {
                    mma16816(acc[mi][2 * g],     aH[mi], &bl[0]);
                    mma16816(acc[mi][2 * g + 1], aH[mi], &bl[2]);
                }
#pragma unroll
                for (int mi = 0; mi < 4; mi++) {
                    mma16816(acc[mi][2 * g],     aL[mi], &bh[0]);
                    mma16816(acc[mi][2 * g + 1], aL[mi], &bh[2]);
                }
            }
        }
    }

    const int qr = lane >> 2, qc = lane & 3;
    if (mode == 0) {
#pragma unroll
        for (int mi = 0; mi < 4; mi++)
#pragma unroll
            for (int ni = 0; ni < 4; ni++) {
                int row = row0 + wm * 64 + mi * 16 + qr;
                int col = col0 + wn * 32 + ni * 8 + qc * 2;
                float2 bv = *(const float2*)(bias + col);
                float2 v0, v1;
                v0.x = acc[mi][ni][0] + bv.x;  v0.y = acc[mi][ni][1] + bv.y;
                v1.x = acc[mi][ni][2] + bv.x;  v1.y = acc[mi][ni][3] + bv.y;
                *(float2*)(C + (size_t)row * Nld + col) = v0;
                *(float2*)(C + (size_t)(row + 8) * Nld + col) = v1;
            }
    } else {
        int t = col0 >> 10;
        __nv_bfloat16* oh = (t == 0) ? oqh : (t == 1) ? okh : ovh;
        __nv_bfloat16* ol = (t == 0) ? oql : (t == 1) ? okl : ovl;
        float sc = (t == 0) ? 0.125f : 1.0f;
#pragma unroll
        for (int mi = 0; mi < 4; mi++)
#pragma unroll
            for (int ni = 0; ni < 4; ni++) {
                int row = row0 + wm * 64 + mi * 16 + qr;
                int gcol = col0 + wn * 32 + ni * 8 + qc * 2;
                int lcol = gcol & 1023;
                float2 bv = *(const float2*)(bias + gcol);
                float x0 = (acc[mi][ni][0] + bv.x) * sc;
                float x1 = (acc[mi][ni][1] + bv.y) * sc;
                float x2 = (acc[mi][ni][2] + bv.x) * sc;
                float x3 = (acc[mi][ni][3] + bv.y) * sc;
                __nv_bfloat16 h0 = __float2bfloat16(x0), h1 = __float2bfloat16(x1);
                __nv_bfloat16 h2 = __float2bfloat16(x2), h3 = __float2bfloat16(x3);
                size_t i0 = (size_t)row * DD + lcol;
                size_t i1 = (size_t)(row + 8) * DD + lcol;
                *(__nv_bfloat162*)(oh + i0) = __halves2bfloat162(h0, h1);
                *(__nv_bfloat162*)(oh + i1) = __halves2bfloat162(h2, h3);
                *(__nv_bfloat162*)(ol + i0) = __floats2bfloat162_rn(
                    x0 - __bfloat162float(h0), x1 - __bfloat162float(h1));
                *(__nv_bfloat162*)(ol + i1) = __floats2bfloat162_rn(
                    x2 - __bfloat162float(h2), x3 - __bfloat162float(h3));
            }
    }
}

// ---------------------------------------------------------------------------
// Flash attention with mma.sync, bf16x3, causal (unchanged from round 5)
// ---------------------------------------------------------------------------
#define ATT_TILE_B 16384
#define ATT_KV_STAGE (4 * ATT_TILE_B)
#define ATT_SMEM (2 * ATT_TILE_B + 2 * ATT_KV_STAGE)   // 163840

__device__ __forceinline__ uint32_t sw128(uint32_t tb, int row, int chunk) {
    return tb + row * 128 + ((chunk ^ (row & 7)) << 4);
}
__device__ __forceinline__ uint32_t fa_a(uint32_t tb, int m0, int ks, int lane) {
    int row = m0 + (lane & 15);
    return sw128(tb, row, ks * 2 + (lane >> 4));
}
__device__ __forceinline__ uint32_t fa_b(uint32_t tb, int n0, int ks, int lane) {
    int row = n0 + (lane & 7) + ((lane >> 4) << 3);
    return sw128(tb, row, ks * 2 + ((lane >> 3) & 1));
}
__device__ __forceinline__ uint32_t fa_v(uint32_t tb, int kv0, int hd0, int lane) {
    int row = kv0 + (((lane >> 3) & 1) << 3) + (lane & 7);
    return sw128(tb, row, (hd0 >> 3) + (lane >> 4));
}

__global__ __launch_bounds__(256, 1) void flash_attn_mma(
    const __nv_bfloat16* __restrict__ qh, const __nv_bfloat16* __restrict__ ql,
    const __nv_bfloat16* __restrict__ kh, const __nv_bfloat16* __restrict__ kl,
    const __nv_bfloat16* __restrict__ vh, const __nv_bfloat16* __restrict__ vl,
    __nv_bfloat16* __restrict__ yh, __nv_bfloat16* __restrict__ yl)
{
    extern __shared__ __align__(1024) char smraw[];
    const uint32_t sb = smem_u32(smraw);
    const int qt = blockIdx.x, h = blockIdx.y, b = blockIdx.z;
    const int tid = threadIdx.x, lane = tid & 31, w = tid >> 5;
    const size_t rowbase = (size_t)(b * SS) + qt * 128;
    const int hoff = h * HDIM;

    const uint32_t sQh = sb, sQl = sb + ATT_TILE_B;
    const uint32_t sKV = sb + 2 * ATT_TILE_B;

    {
        const __nv_bfloat16* qs[2] = {qh, ql};
        for (int i = tid; i < 2048; i += 256) {
            int t = i >> 10, idx = i & 1023, r = idx >> 3, ch = idx & 7;
            CP16(sw128(t ? sQl : sQh, r, ch),
                 qs[t] + (rowbase + r) * DD + hoff + ch * 8);
        }
        CP_COMMIT();
    }

    const __nv_bfloat16* kvs[4] = {kh, kl, vh, vl};
    auto fillkv = [&](int kt, int s) {
        uint32_t stg = sKV + s * ATT_KV_STAGE;
        size_t kvrow = (size_t)(b * SS) + (size_t)kt * 128;
        for (int i = tid; i < 4096; i += 256) {
            int t = i >> 10, idx = i & 1023, r = idx >> 3, ch = idx & 7;
            CP16(sw128(stg + t * ATT_TILE_B, r, ch),
                 kvs[t] + (kvrow + r) * DD + hoff + ch * 8);
        }
        CP_COMMIT();
    };

    fillkv(0, 0);
    if (qt >= 1) fillkv(1, 1);

    float o[8][4];
#pragma unroll
    for (int i = 0; i < 8; i++)
#pragma unroll
        for (int q = 0; q < 4; q++) o[i][q] = 0.0f;
    float mrow[2] = {-1e30f, -1e30f};
    float lrow[2] = {0.0f, 0.0f};

    uint32_t aQh[4][4], aQl[4][4];
    const int qr = lane >> 2, qc = lane & 3;

    for (int kt = 0; kt <= qt; kt++) {
        int s = kt & 1;
        if (kt + 1 <= qt) { CP_WAIT(1); } else { CP_WAIT(0); }
        __syncthreads();

        if (kt == 0) {
#pragma unroll
            for (int ks = 0; ks < 4; ks++) {
                ldsm4(aQh[ks], fa_a(sQh, w * 16, ks, lane));
                ldsm4(aQl[ks], fa_a(sQl, w * 16, ks, lane));
            }
        }

        uint32_t tKh = sKV + s * ATT_KV_STAGE;
        uint32_t tKl = tKh + ATT_TILE_B;
        uint32_t tVh = tKh + 2 * ATT_TILE_B;
        uint32_t tVl = tKh + 3 * ATT_TILE_B;

        float sfr[16][4];
#pragma unroll
        for (int i = 0; i < 16; i++)
#pragma unroll
            for (int q = 0; q < 4; q++) sfr[i][q] = 0.0f;

#pragma unroll
        for (int ks = 0; ks < 4; ks++)
#pragma unroll
            for (int np = 0; np < 4; np++) {
                int ng0 = 2 * np, ng1 = 2 * np + 1;
                uint32_t bhA[4], blA[4], bhB[4], blB[4];
                ldsm4(bhA, fa_b(tKh, ng0 * 16, ks, lane));
                ldsm4(blA, fa_b(tKl, ng0 * 16, ks, lane));
                ldsm4(bhB, fa_b(tKh, ng1 * 16, ks, lane));
                ldsm4(blB, fa_b(tKl, ng1 * 16, ks, lane));
                mma16816(sfr[2 * ng0],     aQh[ks], &bhA[0]);
                mma16816(sfr[2 * ng0 + 1], aQh[ks], &bhA[2]);
                mma16816(sfr[2 * ng1],     aQh[ks], &bhB[0]);
                mma16816(sfr[2 * ng1 + 1], aQh[ks], &bhB[2]);
                mma16816(sfr[2 * ng0],     aQh[ks], &blA[0]);
                mma16816(sfr[2 * ng0 + 1], aQh[ks], &blA[2]);
                mma16816(sfr[2 * ng1],     aQh[ks], &blB[0]);
                mma16816(sfr[2 * ng1 + 1], aQh[ks], &blB[2]);
                mma16816(sfr[2 * ng0],     aQl[ks], &bhA[0]);
                mma16816(sfr[2 * ng0 + 1], aQl[ks], &bhA[2]);
                mma16816(sfr[2 * ng1],     aQl[ks], &bhB[0]);
                mma16816(sfr[2 * ng1 + 1], aQl[ks], &bhB[2]);
            }

        if (kt == qt) {
            int r0 = w * 16 + qr;
#pragma unroll
            for (int nf = 0; nf < 16; nf++) {
                int c0 = nf * 8 + qc * 2;
                if (c0 > r0)     sfr[nf][0] = -1e30f;
                if (c0 + 1 > r0) sfr[nf][1] = -1e30f;
                if (c0 > r0 + 8)     sfr[nf][2] = -1e30f;
                if (c0 + 1 > r0 + 8) sfr[nf][3] = -1e30f;
            }
        }

        float tm0 = -1e30f, tm1 = -1e30f;
#pragma unroll
        for (int nf = 0; nf < 16; nf++) {
            tm0 = fmaxf(tm0, fmaxf(sfr[nf][0], sfr[nf][1]));
            tm1 = fmaxf(tm1, fmaxf(sfr[nf][2], sfr[nf][3]));
        }
#pragma unroll
        for (int off = 1; off <= 2; off <<= 1) {
            tm0 = fmaxf(tm0, __shfl_xor_sync(0xffffffffu, tm0, off));
            tm1 = fmaxf(tm1, __shfl_xor_sync(0xffffffffu, tm1, off));
        }
        float mn0 = fmaxf(mrow[0], tm0), mn1 = fmaxf(mrow[1], tm1);
        float al0 = __expf(mrow[0] - mn0), al1 = __expf(mrow[1] - mn1);
        mrow[0] = mn0; mrow[1] = mn1;

        float rs0 = 0.0f, rs1 = 0.0f;
#pragma unroll
        for (int nf = 0; nf < 16; nf++) {
            sfr[nf][0] = __expf(sfr[nf][0] - mn0);
            sfr[nf][1] = __expf(sfr[nf][1] - mn0);
            sfr[nf][2] = __expf(sfr[nf][2] - mn1);
            sfr[nf][3] = __expf(sfr[nf][3] - mn1);
            rs0 += sfr[nf][0] + sfr[nf][1];
            rs1 += sfr[nf][2] + sfr[nf][3];
        }
#pragma unroll
        for (int off = 1; off <= 2; off <<= 1) {
            rs0 += __shfl_xor_sync(0xffffffffu, rs0, off);
            rs1 += __shfl_xor_sync(0xffffffffu, rs1, off);
        }
        lrow[0] = lrow[0] * al0 + rs0;
        lrow[1] = lrow[1] * al1 + rs1;
#pragma unroll
        for (int i = 0; i < 8; i++) {
            o[i][0] *= al0; o[i][1] *= al0;
            o[i][2] *= al1; o[i][3] *= al1;
        }

#pragma unroll
        for (int ks = 0; ks < 8; ks++) {
            const float* f0 = sfr[2 * ks];
            const float* f1 = sfr[2 * ks + 1];
            uint32_t phx[4], plx[4];
            phx[0] = pack_bf2(f0[0], f0[1]);
            phx[1] = pack_bf2(f0[2], f0[3]);
            phx[2] = pack_bf2(f1[0], f1[1]);
            phx[3] = pack_bf2(f1[2], f1[3]);
            {
                __nv_bfloat162 h0 = *(__nv_bfloat162*)&phx[0];
                __nv_bfloat162 h1 = *(__nv_bfloat162*)&phx[1];
                __nv_bfloat162 h2 = *(__nv_bfloat162*)&phx[2];
                __nv_bfloat162 h3 = *(__nv_bfloat162*)&phx[3];
                plx[0] = pack_bf2(f0[0] - __bfloat162float(h0.x), f0[1] - __bfloat162float(h0.y));
                plx[1] = pack_bf2(f0[2] - __bfloat162float(h1.x), f0[3] - __bfloat162float(h1.y));
                plx[2] = pack_bf2(f1[0] - __bfloat162float(h2.x), f1[1] - __bfloat162float(h2.y));
                plx[3] = pack_bf2(f1[2] - __bfloat162float(h3.x), f1[3] - __bfloat162float(h3.y));
            }
#pragma unroll
            for (int gp = 0; gp < 2; gp++) {
                int ng0 = 2 * gp, ng1 = 2 * gp + 1;
                uint32_t vhA[4], vlA[4], vhB[4], vlB[4];
                ldsm4t(vhA, fa_v(tVh, ks * 16, ng0 * 16, lane));
                ldsm4t(vlA, fa_v(tVl, ks * 16, ng0 * 16, lane));
                ldsm4t(vhB, fa_v(tVh, ks * 16, ng1 * 16, lane));
                ldsm4t(vlB, fa_v(tVl, ks * 16, ng1 * 16, lane));
                mma16816(o[2 * ng0],     phx, &vhA[0]);
                mma16816(o[2 * ng0 + 1], phx, &vhA[2]);
                mma16816(o[2 * ng1],     phx, &vhB[0]);
                mma16816(o[2 * ng1 + 1], phx, &vhB[2]);
                mma16816(o[2 * ng0],     plx, &vhA[0]);
                mma16816(o[2 * ng0 + 1], plx, &vhA[2]);
                mma16816(o[2 * ng1],     plx, &vhB[0]);
                mma16816(o[2 * ng1 + 1], plx, &vhB[2]);
                mma16816(o[2 * ng0],     phx, &vlA[0]);
                mma16816(o[2 * ng0 + 1], phx, &vlA[2]);
                mma16816(o[2 * ng1],     phx, &vlB[0]);
                mma16816(o[2 * ng1 + 1], phx, &vlB[2]);
            }
        }

        __syncthreads();
        if (kt + 2 <= qt) fillkv(kt + 2, s);
    }

    float inv0 = 1.0f / lrow[0];
    float inv1 = 1.0f / lrow[1];
    size_t r0 = rowbase + w * 16 + qr;
#pragma unroll
    for (int i = 0; i < 8; i++) {
        int col = hoff + i * 8 + qc * 2;
        float x0 = o[i][0] * inv0, x1 = o[i][1] * inv0;
        float x2 = o[i][2] * inv1, x3 = o[i][3] * inv1;
        __nv_bfloat16 h0 = __float2bfloat16(x0), h1 = __float2bfloat16(x1);
        __nv_bfloat16 h2 = __float2bfloat16(x2), h3 = __float2bfloat16(x3);
        size_t i0 = r0 * DD + col;
        size_t i1 = (r0 + 8) * DD + col;
        *(__nv_bfloat162*)(yh + i0) = __halves2bfloat162(h0, h1);
        *(__nv_bfloat162*)(yh + i1) = __halves2bfloat162(h2, h3);
        *(__nv_bfloat162*)(yl + i0) = __floats2bfloat162_rn(
            x0 - __bfloat162float(h0), x1 - __bfloat162float(h1));
        *(__nv_bfloat162*)(yl + i1) = __floats2bfloat162_rn(
            x2 - __bfloat162float(h2), x3 - __bfloat162float(h3));
    }
}

// ---------------------------------------------------------------------------
extern "C" void kernel_launch(void* const* d_in, const int* in_sizes, int n_in,
                              void* d_out, int out_size)
{
    const float* x      = (const float*)d_in[0];
    const float* W_attn = (const float*)d_in[1];
    const float* b_attn = (const float*)d_in[2];
    const float* W_proj = (const float*)d_in[3];
    const float* b_proj = (const float*)d_in[4];
    float* out = (float*)d_out;

    __nv_bfloat16 *xh, *xl, *qhp, *qlp, *khp, *klp, *vhp, *vlp, *yhp, *ylp;
    __nv_bfloat16 *wah, *wal, *wph, *wpl;
    cudaGetSymbolAddress((void**)&xh,  g_xh);
    cudaGetSymbolAddress((void**)&xl,  g_xl);
    cudaGetSymbolAddress((void**)&qhp, g_qh);
    cudaGetSymbolAddress((void**)&qlp, g_ql);
    cudaGetSymbolAddress((void**)&khp, g_kh);
    cudaGetSymbolAddress((void**)&klp, g_kl);
    cudaGetSymbolAddress((void**)&vhp, g_vh);
    cudaGetSymbolAddress((void**)&vlp, g_vl);
    cudaGetSymbolAddress((void**)&yhp, g_yh);
    cudaGetSymbolAddress((void**)&ylp, g_yl);
    cudaGetSymbolAddress((void**)&wah, g_wah);
    cudaGetSymbolAddress((void**)&wal, g_wal);
    cudaGetSymbolAddress((void**)&wph, g_wph);
    cudaGetSymbolAddress((void**)&wpl, g_wpl);

    cudaFuncSetAttribute(gemm_mma_bf16x3, cudaFuncAttributeMaxDynamicSharedMemorySize,
                         (int)GEMM_SMEM);
    cudaFuncSetAttribute(flash_attn_mma, cudaFuncAttributeMaxDynamicSharedMemorySize,
                         (int)ATT_SMEM);

    split_kernel<<<(MROWS * KDIM / 4 + 255) / 256, 256>>>(x, xh, xl, MROWS * KDIM / 4);
    wsplit_t<<<dim3(3 * DD / 32, KDIM / 32), dim3(32, 8)>>>(W_attn, wah, wal, KDIM, 3 * DD);
    wsplit_t<<<dim3(DD / 32, KDIM / 32), dim3(32, 8)>>>(W_proj, wph, wpl, KDIM, DD);

    gemm_mma_bf16x3<<<dim3(3 * DD / GBN, MROWS / GBM), 256, GEMM_SMEM>>>(
        xh, xl, wah, wal, b_attn, nullptr, 3 * DD, 1,
        qhp, qlp, khp, klp, vhp, vlp);

    flash_attn_mma<<<dim3(SS / 128, HH, BB), 256, ATT_SMEM>>>(
        qhp, qlp, khp, klp, vhp, vlp, yhp, ylp);

    gemm_mma_bf16x3<<<dim3(DD / GBN, MROWS / GBM), 256, GEMM_SMEM>>>(
        yhp, ylp, wph, wpl, b_proj, out, DD, 0,
        nullptr, nullptr, nullptr, nullptr, nullptr, nullptr);
}